// round 5
// baseline (speedup 1.0000x reference)
#include <cuda_runtime.h>
#include <math.h>

// Problem constants
#define BQ      1024
#define DDIM    128
#define NKEYS   200000
#define HFDIM   168
#define TOPK    16
#define MT      128          // queries per block
#define KT      128          // keys per tile
#define CHUNK   2048
#define NCHUNKS 98
#define QTILES  (BQ/MT)      // 8
#define NPAIRS  (QTILES*NCHUNKS)   // 784
#define NTHR    256
#define GRID_P  296

// -------- dynamic SMEM layout (bytes) --------
// union: [Qs2 32x130 f32x2 (33280) | Ks 32x132 f32 (16896)] overlapped with Sim[128][132] (67584)
#define OFF_KS    33280
#define OFF_SS    67584
#define OFF_TOPV  68096
#define OFF_TOPI  76800
#define OFF_WORK  85504
#define SMEM_SZ   85536

// -------- scratch --------
__device__ float g_qnT[DDIM * BQ];
__device__ float g_scale[NKEYS];
__device__ unsigned long long g_cand[(size_t)BQ * NCHUNKS * TOPK];
__device__ int g_ts64;
__device__ unsigned int g_work;

// -------- helpers --------
__device__ __forceinline__ unsigned int fkey(float f) {
    unsigned int u = __float_as_uint(f);
    return (u & 0x80000000u) ? ~u : (u | 0x80000000u);
}
__device__ __forceinline__ float funkey(unsigned int u) {
    return (u & 0x80000000u) ? __uint_as_float(u ^ 0x80000000u)
                             : __uint_as_float(~u);
}
#define FMA2(acc, a, b) \
    asm("fma.rn.f32x2 %0, %1, %2, %0;" : "+l"(acc) : "l"(a), "l"(b))
#define MUL2(r, a, b) \
    asm("mul.rn.f32x2 %0, %1, %2;" : "=l"(r) : "l"(a), "l"(b))
#define NEG_INF __int_as_float(0xff800000)

// -------- kernel 0: detect ts dtype + reset work counter --------
__global__ void k_detect(const unsigned int* tsw) {
    if (threadIdx.x == 0) {
        int all0 = 1;
        for (int i = 0; i < 64; i++)
            if (tsw[2 * i + 1] != 0u) { all0 = 0; break; }
        g_ts64 = all0;
        g_work = 0u;
    }
}

// -------- kernel 1: normalize queries -> transposed --------
__global__ void k_normq(const float* __restrict__ query) {
    int b = blockIdx.x;
    int d = threadIdx.x;
    float v = query[b * DDIM + d];
    float s = v * v;
    #pragma unroll
    for (int o = 16; o; o >>= 1) s += __shfl_xor_sync(0xffffffffu, s, o);
    __shared__ float ws[4];
    if ((d & 31) == 0) ws[d >> 5] = s;
    __syncthreads();
    float tot = ws[0] + ws[1] + ws[2] + ws[3];
    float n = fmaxf(sqrtf(tot), 1e-12f);
    g_qnT[d * BQ + b] = v / n;
}

// -------- kernel 2: per-key scale = decay / ||k|| --------
__global__ void k_scale(const float* __restrict__ keys, const void* ts,
                        const int* gsp, int has_gs) {
    int gw = (blockIdx.x * blockDim.x + threadIdx.x) >> 5;
    int lane = threadIdx.x & 31;
    if (gw >= NKEYS) return;
    float4 a = ((const float4*)(keys + (size_t)gw * DDIM))[lane];
    float s = a.x * a.x + a.y * a.y + a.z * a.z + a.w * a.w;
    #pragma unroll
    for (int o = 16; o; o >>= 1) s += __shfl_xor_sync(0xffffffffu, s, o);
    if (lane == 0) {
        long long t = g_ts64 ? ((const long long*)ts)[gw]
                             : (long long)((const int*)ts)[gw];
        int gs = has_gs ? gsp[0] : 1000;
        float age = (float)(gs - (int)t);
        float dec = powf(0.995f, age);
        float nr = fmaxf(sqrtf(s), 1e-12f);
        g_scale[gw] = dec / nr;
    }
}

// -------- kernel 3: persistent fused GEMM (f32x2) + chunk top-16 --------
// 256 threads; thread (tx=tid&15, ty=tid>>4) owns queries {i*32+ty*2,+1}
// (i=0..3) and keys {tx*8..tx*8+7}. K SMEM swizzled: logical key row L of
// d-column d stored at L ^ (4*((d&31)>>2)) -> conflict-free staging stores.
__global__ void __launch_bounds__(NTHR, 2)
k_gemm_topk(const float* __restrict__ keys) {
    extern __shared__ __align__(16) unsigned char sm[];
    float2* Qs2  = (float2*)sm;                   // [32][130] dup pairs
    float*  Ks   = (float*)(sm + OFF_KS);         // [32][132] swizzled
    float*  Sim  = (float*)sm;                    // [128][132] (union)
    float*  Ss   = (float*)(sm + OFF_SS);         // [128]
    float*  topv = (float*)(sm + OFF_TOPV);       // [128][17]
    int*    topi = (int*)(sm + OFF_TOPI);         // [128][17]
    unsigned int* swork = (unsigned int*)(sm + OFF_WORK);

    int tid = threadIdx.x;
    int tx = tid & 15;
    int ty = tid >> 4;     // 0..15

    for (;;) {
        __syncthreads();
        if (tid == 0) *swork = atomicAdd(&g_work, 1u);
        __syncthreads();
        unsigned int p = *swork;
        if (p >= NPAIRS) break;
        int chunk = p >> 3;
        int qtile = p & 7;
        int qbase = qtile * MT;
        int c0 = chunk * CHUNK;

        if (tid < 128) {
            #pragma unroll
            for (int j = 0; j < TOPK; j++) {
                topv[tid * 17 + j] = NEG_INF;
                topi[tid * 17 + j] = 0;
            }
        }

        for (int t0 = 0; t0 < CHUNK && c0 + t0 < NKEYS; t0 += KT) {
            int n0 = c0 + t0;
            int nk = min(KT, NKEYS - n0);
            __syncthreads();       // prior scan done (Sim union reuse)
            if (tid < 128) Ss[tid] = (n0 + tid < NKEYS) ? g_scale[n0 + tid] : 0.0f;

            unsigned long long acc[8][4];
            #pragma unroll
            for (int i = 0; i < 8; i++)
                #pragma unroll
                for (int j = 0; j < 4; j++) acc[i][j] = 0ull;

            for (int stage = 0; stage < 4; ++stage) {
                int ds = stage * 32;
                __syncthreads();
                // Q staging: coalesced LDG, duplicated-pair STS.64
                {
                    int dq = tid >> 3;         // 0..31
                    int j0 = tid & 7;
                    #pragma unroll
                    for (int i = 0; i < 4; i++) {
                        int j = j0 + 8 * i;    // float4 col 0..31
                        float4 v = *(const float4*)&g_qnT[(ds + dq) * BQ + qbase + j * 4];
                        float2* dst = &Qs2[dq * 130 + j * 4];
                        dst[0] = make_float2(v.x, v.x);
                        dst[1] = make_float2(v.y, v.y);
                        dst[2] = make_float2(v.z, v.z);
                        dst[3] = make_float2(v.w, v.w);
                    }
                }
                // K staging: coalesced LDG (8 lanes x 16B per row), swizzled STS
                {
                    int c = tid & 7;           // float4 col -> d = c*4+w
                    int r = tid >> 3;          // 0..31
                    int sw = 4 * c;            // swizzle for all 4 w of this c
                    #pragma unroll
                    for (int i = 0; i < 4; i++) {
                        int row = i * 32 + r;
                        int krow = min(n0 + row, NKEYS - 1);
                        float4 v = *(const float4*)&keys[(size_t)krow * DDIM + ds + c * 4];
                        int pr = row ^ sw;
                        Ks[(c * 4 + 0) * 132 + pr] = v.x;
                        Ks[(c * 4 + 1) * 132 + pr] = v.y;
                        Ks[(c * 4 + 2) * 132 + pr] = v.z;
                        Ks[(c * 4 + 3) * 132 + pr] = v.w;
                    }
                }
                __syncthreads();
                #pragma unroll 4
                for (int sd = 0; sd < 32; ++sd) {
                    int swz = sd & 28;         // 4*(sd>>2)
                    // Q: 2 distinct 16B addrs per instr, broadcast -> ~1 wf
                    unsigned long long qa[8];
                    const float2* qrow = Qs2 + sd * 130 + ty * 2;
                    #pragma unroll
                    for (int i = 0; i < 4; i++) {
                        ulonglong2 t = *(const ulonglong2*)(qrow + i * 32);
                        qa[2 * i]     = t.x;
                        qa[2 * i + 1] = t.y;
                    }
                    // K: un-swizzle with XOR; 16B-aligned groups preserved
                    unsigned long long kb[4];
                    const float* krow_s = Ks + sd * 132;
                    {
                        ulonglong2 t0 = *(const ulonglong2*)(krow_s + ((tx * 8) ^ swz));
                        ulonglong2 t1 = *(const ulonglong2*)(krow_s + ((tx * 8 + 4) ^ swz));
                        kb[0] = t0.x; kb[1] = t0.y;
                        kb[2] = t1.x; kb[3] = t1.y;
                    }
                    #pragma unroll
                    for (int i = 0; i < 8; i++)
                        #pragma unroll
                        for (int j = 0; j < 4; j++)
                            FMA2(acc[i][j], qa[i], kb[j]);
                }
            }
            __syncthreads();   // all FMAs done before Sim overwrites union

            // scale + store sims (STS.128)
            {
                ulonglong2 ss0 = *(const ulonglong2*)&Ss[tx * 8];
                ulonglong2 ss1 = *(const ulonglong2*)&Ss[tx * 8 + 4];
                #pragma unroll
                for (int i8 = 0; i8 < 8; i8++) {
                    int q = (i8 >> 1) * 32 + ty * 2 + (i8 & 1);
                    ulonglong2 r0, r1;
                    MUL2(r0.x, acc[i8][0], ss0.x);
                    MUL2(r0.y, acc[i8][1], ss0.y);
                    MUL2(r1.x, acc[i8][2], ss1.x);
                    MUL2(r1.y, acc[i8][3], ss1.y);
                    *(ulonglong2*)&Sim[q * 132 + tx * 8]     = r0;
                    *(ulonglong2*)&Sim[q * 132 + tx * 8 + 4] = r1;
                }
            }
            __syncthreads();

            // rotated per-query scan: col=(tid+j)&127 -> bank 5*tid+j, CF
            if (tid < 128) {
                float thr = topv[tid * 17 + TOPK - 1];
                const float* row = &Sim[tid * 132];
                #pragma unroll 4
                for (int j = 0; j < KT; j++) {
                    int col = (tid + j) & 127;
                    float v = row[col];
                    if (v > thr && col < nk) {
                        int kidx = n0 + col;
                        int pos = TOPK - 1;
                        while (pos > 0 && topv[tid * 17 + pos - 1] < v) {
                            topv[tid * 17 + pos] = topv[tid * 17 + pos - 1];
                            topi[tid * 17 + pos] = topi[tid * 17 + pos - 1];
                            pos--;
                        }
                        topv[tid * 17 + pos] = v;
                        topi[tid * 17 + pos] = kidx;
                        thr = topv[tid * 17 + TOPK - 1];
                    }
                }
            }
        }
        __syncthreads();

        if (tid < 128) {
            int b = qbase + tid;
            unsigned long long* dst = &g_cand[((size_t)b * NCHUNKS + chunk) * TOPK];
            #pragma unroll
            for (int j = 0; j < TOPK; j++) {
                unsigned long long hv =
                    (unsigned long long)fkey(topv[tid * 17 + j]) << 32;
                dst[j] = hv | (unsigned long long)(0xFFFFFFFFu -
                                (unsigned int)topi[tid * 17 + j]);
            }
        }
    }
}

// -------- kernel 4: merge candidates + weighted gather --------
#define NCAND (NCHUNKS * TOPK)

__global__ void __launch_bounds__(256)
k_merge(const float* __restrict__ values, float* __restrict__ out) {
    __shared__ unsigned long long cb[NCAND];
    __shared__ unsigned long long wred[8];
    __shared__ float smv[TOPK];
    __shared__ int   sidx[TOPK];
    __shared__ float w[TOPK];

    int b = blockIdx.x, tid = threadIdx.x;
    int lane = tid & 31, wid = tid >> 5;
    const unsigned long long* src = &g_cand[(size_t)b * NCAND];
    for (int i = tid; i < NCAND; i += 256) cb[i] = src[i];
    __syncthreads();

    for (int r = 0; r < TOPK; r++) {
        unsigned long long m = 0ull;
        for (int i = tid; i < NCAND; i += 256) {
            unsigned long long v = cb[i];
            if (v > m) m = v;
        }
        #pragma unroll
        for (int o = 16; o; o >>= 1) {
            unsigned long long t = __shfl_xor_sync(0xffffffffu, m, o);
            if (t > m) m = t;
        }
        if (lane == 0) wred[wid] = m;
        __syncthreads();
        unsigned long long top = wred[0];
        #pragma unroll
        for (int i = 1; i < 8; i++) if (wred[i] > top) top = wred[i];
        for (int i = tid; i < NCAND; i += 256)
            if (cb[i] == top) cb[i] = 0ull;
        if (tid == 0) {
            float s = funkey((unsigned int)(top >> 32));
            int idx = (int)(0xFFFFFFFFu - (unsigned int)(top & 0xFFFFFFFFu));
            smv[r] = (s >= 0.0f) ? s : 0.0f;
            sidx[r] = idx;
        }
        __syncthreads();
    }

    if (tid == 0) {
        float su = 0.0f;
        #pragma unroll
        for (int r = 0; r < TOPK; r++) su += smv[r];
        su += 1e-8f;
        #pragma unroll
        for (int r = 0; r < TOPK; r++) w[r] = smv[r] / su;
    }
    __syncthreads();

    if (tid < HFDIM) {
        float a = 0.0f;
        #pragma unroll
        for (int r = 0; r < TOPK; r++)
            a += w[r] * values[(size_t)sidx[r] * HFDIM + tid];
        out[(size_t)b * HFDIM + tid] = a;
    }
}

// -------- launch --------
extern "C" void kernel_launch(void* const* d_in, const int* in_sizes, int n_in,
                              void* d_out, int out_size) {
    const float* query  = (const float*)d_in[0];
    const float* keys   = (const float*)d_in[1];
    const float* values = (const float*)d_in[2];
    const void*  ts     = d_in[3];
    const int*   gsp    = (n_in > 4) ? (const int*)d_in[4] : nullptr;

    cudaFuncSetAttribute(k_gemm_topk,
                         cudaFuncAttributeMaxDynamicSharedMemorySize, SMEM_SZ);

    k_detect<<<1, 32>>>((const unsigned int*)ts);
    k_normq<<<BQ, DDIM>>>(query);
    k_scale<<<(NKEYS * 32 + 255) / 256, 256>>>(keys, ts, gsp, gsp != nullptr);
    k_gemm_topk<<<GRID_P, NTHR, SMEM_SZ>>>(keys);
    k_merge<<<BQ, 256>>>(values, (float*)d_out);
}

// round 6
// speedup vs baseline: 1.7850x; 1.7850x over previous
#include <cuda_runtime.h>
#include <cuda_bf16.h>
#include <math.h>

// Problem constants
#define BQ      1024
#define DDIM    128
#define NKEYS   200000
#define HFDIM   168
#define TOPK    16
#define MTOP    48           // merged approx candidates to rescore exactly
#define CHUNK   2048
#define NCHUNKS 98           // 97*2048 + 1344; every 64-key tile is full
#define QTILES  8            // 1024/128
#define NPAIRS  (QTILES*NCHUNKS)   // 784
#define FTHR    128
#define GRID_F  296

// -------- filter kernel SMEM layout (bytes) --------
#define OFF_K     34816              // Qs: bf16 [128][136]
#define OFF_SIM   52224              // Ks: bf16 [64][136]
#define OFF_TOPV  87040              // Sim: f32 [128][68]
#define OFF_TOPI  95744
#define OFF_WORK  104448
#define SMEM_SZ   104464

// -------- scratch --------
__device__ float g_qn[BQ * DDIM];                 // normalized queries fp32 (row-major)
__device__ __nv_bfloat16 g_qb[BQ * DDIM];         // normalized queries bf16
__device__ __nv_bfloat16 g_kbd[(size_t)NKEYS * DDIM];  // keys * decay/||k||, bf16
__device__ float g_scale[NKEYS];                  // decay/||k|| fp32 (for rescore)
__device__ unsigned long long g_cand[(size_t)BQ * NCHUNKS * TOPK];
__device__ int g_ts64;
__device__ unsigned int g_work;

// -------- helpers --------
__device__ __forceinline__ unsigned int fkey(float f) {
    unsigned int u = __float_as_uint(f);
    return (u & 0x80000000u) ? ~u : (u | 0x80000000u);
}
__device__ __forceinline__ float funkey(unsigned int u) {
    return (u & 0x80000000u) ? __uint_as_float(u ^ 0x80000000u)
                             : __uint_as_float(~u);
}
__device__ __forceinline__ unsigned int su32(const void* p) {
    unsigned int r;
    asm("{.reg .u64 t; cvta.to.shared.u64 t, %1; cvt.u32.u64 %0, t;}"
        : "=r"(r) : "l"(p));
    return r;
}
#define NEG_INF __int_as_float(0xff800000)

// -------- kernel 0: detect ts dtype + reset work counter --------
__global__ void k_detect(const unsigned int* tsw) {
    if (threadIdx.x == 0) {
        int all0 = 1;
        for (int i = 0; i < 64; i++)
            if (tsw[2 * i + 1] != 0u) { all0 = 0; break; }
        g_ts64 = all0;
        g_work = 0u;
    }
}

// -------- kernel 1: normalize queries (fp32 + bf16 copies) --------
__global__ void k_normq(const float* __restrict__ query) {
    int b = blockIdx.x;
    int d = threadIdx.x;
    float v = query[b * DDIM + d];
    float s = v * v;
    #pragma unroll
    for (int o = 16; o; o >>= 1) s += __shfl_xor_sync(0xffffffffu, s, o);
    __shared__ float ws[4];
    if ((d & 31) == 0) ws[d >> 5] = s;
    __syncthreads();
    float tot = ws[0] + ws[1] + ws[2] + ws[3];
    float n = fmaxf(sqrtf(tot), 1e-12f);
    float q = v / n;
    g_qn[b * DDIM + d] = q;
    g_qb[b * DDIM + d] = __float2bfloat16_rn(q);
}

// -------- kernel 2: per-key scale + bf16 decayed-normalized keys --------
__global__ void k_scale(const float* __restrict__ keys, const void* ts,
                        const int* gsp, int has_gs) {
    int gw = (blockIdx.x * blockDim.x + threadIdx.x) >> 5;
    int lane = threadIdx.x & 31;
    if (gw >= NKEYS) return;
    float4 a = ((const float4*)(keys + (size_t)gw * DDIM))[lane];
    float s = a.x * a.x + a.y * a.y + a.z * a.z + a.w * a.w;
    #pragma unroll
    for (int o = 16; o; o >>= 1) s += __shfl_xor_sync(0xffffffffu, s, o);
    float sc;
    if (lane == 0) {
        long long t = g_ts64 ? ((const long long*)ts)[gw]
                             : (long long)((const int*)ts)[gw];
        int gs = has_gs ? gsp[0] : 1000;
        float age = (float)(gs - (int)t);
        float dec = powf(0.995f, age);
        float nr = fmaxf(sqrtf(s), 1e-12f);
        sc = dec / nr;
        g_scale[gw] = sc;
    }
    sc = __shfl_sync(0xffffffffu, sc, 0);
    __nv_bfloat162 p0 = __floats2bfloat162_rn(a.x * sc, a.y * sc);
    __nv_bfloat162 p1 = __floats2bfloat162_rn(a.z * sc, a.w * sc);
    uint2 pk = make_uint2(*(unsigned int*)&p0, *(unsigned int*)&p1);
    *(uint2*)&g_kbd[(size_t)gw * DDIM + lane * 4] = pk;
}

// -------- kernel 3: bf16 MMA filter + per-chunk approx top-16 --------
__global__ void __launch_bounds__(FTHR, 2)
k_filter() {
    extern __shared__ __align__(16) unsigned char sm[];
    __nv_bfloat16* Qs = (__nv_bfloat16*)sm;             // [128][136]
    __nv_bfloat16* Ks = (__nv_bfloat16*)(sm + OFF_K);   // [64][136]
    float* Sim  = (float*)(sm + OFF_SIM);               // [128][68]
    float* topv = (float*)(sm + OFF_TOPV);              // [128][17]
    int*   topi = (int*)(sm + OFF_TOPI);                // [128][17]
    unsigned int* swork = (unsigned int*)(sm + OFF_WORK);

    int tid  = threadIdx.x;
    int warp = tid >> 5;
    int lane = tid & 31;

    for (;;) {
        __syncthreads();
        if (tid == 0) *swork = atomicAdd(&g_work, 1u);
        __syncthreads();
        unsigned int p = *swork;
        if (p >= NPAIRS) break;
        int chunk = p >> 3;
        int qtile = p & 7;
        int qbase = qtile * 128;
        int c0 = chunk * CHUNK;
        int ntiles = (chunk == NCHUNKS - 1) ? 21 : 32;   // all tiles full (64 keys)

        #pragma unroll
        for (int j = 0; j < TOPK; j++) {
            topv[tid * 17 + j] = NEG_INF;
            topi[tid * 17 + j] = 0;
        }
        // load Q tile [128][128] bf16, padded stride 136
        for (int i = tid; i < 128 * 16; i += FTHR) {
            int row = i >> 4, c = i & 15;
            *(uint4*)(Qs + row * 136 + c * 8) =
                *(const uint4*)(g_qb + (qbase + row) * DDIM + c * 8);
        }

        for (int t = 0; t < ntiles; t++) {
            int n0g = c0 + t * 64;
            __syncthreads();   // prior mma (Ks) + prior scan (Sim) complete
            // load K tile [64][128] bf16
            for (int i = tid; i < 64 * 16; i += FTHR) {
                int row = i >> 4, c = i & 15;
                *(uint4*)(Ks + row * 136 + c * 8) =
                    *(const uint4*)(g_kbd + (size_t)(n0g + row) * DDIM + c * 8);
            }
            __syncthreads();

            int q0 = warp * 32;
            float acc[2][8][4];
            #pragma unroll
            for (int mi = 0; mi < 2; mi++)
                #pragma unroll
                for (int nt = 0; nt < 8; nt++)
                    #pragma unroll
                    for (int e = 0; e < 4; e++) acc[mi][nt][e] = 0.0f;

            #pragma unroll
            for (int s8 = 0; s8 < 8; s8++) {
                int ds = s8 * 16;
                unsigned int a[2][4];
                #pragma unroll
                for (int mi = 0; mi < 2; mi++) {
                    int row = q0 + mi * 16 + (lane & 15);
                    int col = ds + ((lane >> 4) << 3);
                    unsigned int ad = su32(Qs + row * 136 + col);
                    asm volatile(
                        "ldmatrix.sync.aligned.m8n8.x4.shared.b16 {%0,%1,%2,%3}, [%4];"
                        : "=r"(a[mi][0]), "=r"(a[mi][1]), "=r"(a[mi][2]), "=r"(a[mi][3])
                        : "r"(ad));
                }
                unsigned int bb[4][4];
                #pragma unroll
                for (int g = 0; g < 4; g++) {
                    int prow = g * 16 + (lane & 7) + ((lane >> 4) << 3);
                    int pcol = ds + (((lane >> 3) & 1) << 3);
                    unsigned int ad = su32(Ks + prow * 136 + pcol);
                    asm volatile(
                        "ldmatrix.sync.aligned.m8n8.x4.shared.b16 {%0,%1,%2,%3}, [%4];"
                        : "=r"(bb[g][0]), "=r"(bb[g][1]), "=r"(bb[g][2]), "=r"(bb[g][3])
                        : "r"(ad));
                }
                #pragma unroll
                for (int mi = 0; mi < 2; mi++)
                    #pragma unroll
                    for (int nt = 0; nt < 8; nt++) {
                        unsigned int b0 = bb[nt >> 1][(nt & 1) * 2];
                        unsigned int b1 = bb[nt >> 1][(nt & 1) * 2 + 1];
                        asm volatile(
                            "mma.sync.aligned.m16n8k16.row.col.f32.bf16.bf16.f32 "
                            "{%0,%1,%2,%3}, {%4,%5,%6,%7}, {%8,%9}, {%0,%1,%2,%3};"
                            : "+f"(acc[mi][nt][0]), "+f"(acc[mi][nt][1]),
                              "+f"(acc[mi][nt][2]), "+f"(acc[mi][nt][3])
                            : "r"(a[mi][0]), "r"(a[mi][1]), "r"(a[mi][2]), "r"(a[mi][3]),
                              "r"(b0), "r"(b1));
                    }
            }
            // store approx sims to Sim[128][68]
            #pragma unroll
            for (int mi = 0; mi < 2; mi++)
                #pragma unroll
                for (int nt = 0; nt < 8; nt++) {
                    int row = q0 + mi * 16 + (lane >> 2);
                    int col = nt * 8 + (lane & 3) * 2;
                    *(float2*)&Sim[row * 68 + col] =
                        make_float2(acc[mi][nt][0], acc[mi][nt][1]);
                    *(float2*)&Sim[(row + 8) * 68 + col] =
                        make_float2(acc[mi][nt][2], acc[mi][nt][3]);
                }
            __syncthreads();

            // scan: thread owns query tid; rotated float4 over 64 cols
            {
                float thr = topv[tid * 17 + TOPK - 1];
                const float* row = &Sim[tid * 68];
                #pragma unroll 4
                for (int j4 = 0; j4 < 16; j4++) {
                    int cg = (tid + j4) & 15;
                    float4 v = *(const float4*)&row[cg * 4];
                    float m01 = fmaxf(v.x, v.y), m23 = fmaxf(v.z, v.w);
                    if (fmaxf(m01, m23) > thr) {
                        #pragma unroll
                        for (int e = 0; e < 4; e++) {
                            float vv = (e == 0) ? v.x : (e == 1) ? v.y
                                     : (e == 2) ? v.z : v.w;
                            if (vv > thr) {
                                int kidx = n0g + cg * 4 + e;
                                int pos = TOPK - 1;
                                while (pos > 0 && topv[tid * 17 + pos - 1] < vv) {
                                    topv[tid * 17 + pos] = topv[tid * 17 + pos - 1];
                                    topi[tid * 17 + pos] = topi[tid * 17 + pos - 1];
                                    pos--;
                                }
                                topv[tid * 17 + pos] = vv;
                                topi[tid * 17 + pos] = kidx;
                                thr = topv[tid * 17 + TOPK - 1];
                            }
                        }
                    }
                }
            }
        }
        __syncthreads();
        {
            int b = qbase + tid;
            unsigned long long* dst = &g_cand[((size_t)b * NCHUNKS + chunk) * TOPK];
            #pragma unroll
            for (int j = 0; j < TOPK; j++) {
                unsigned long long hv =
                    (unsigned long long)fkey(topv[tid * 17 + j]) << 32;
                dst[j] = hv | (unsigned long long)(0xFFFFFFFFu -
                                (unsigned int)topi[tid * 17 + j]);
            }
        }
    }
}

// -------- kernel 4: merge approx top-48, exact rescore, output --------
#define NCAND (NCHUNKS * TOPK)   // 1568

__global__ void __launch_bounds__(128)
k_rescore(const float* __restrict__ keys, const float* __restrict__ values,
          float* __restrict__ out) {
    __shared__ unsigned long long cb[NCAND];
    __shared__ unsigned long long wred[4];
    __shared__ unsigned long long mtop[MTOP];
    __shared__ unsigned long long exact[MTOP];
    __shared__ float qsh[DDIM];
    __shared__ float smv[TOPK];
    __shared__ int   sidx[TOPK];
    __shared__ float w[TOPK];

    int b = blockIdx.x, tid = threadIdx.x;
    int lane = tid & 31, warp = tid >> 5;

    const unsigned long long* src = &g_cand[(size_t)b * NCAND];
    for (int i = tid; i < NCAND; i += 128) cb[i] = src[i];
    qsh[tid] = g_qn[b * DDIM + tid];
    __syncthreads();

    // approx global top-48 (packed keys are unique)
    for (int r = 0; r < MTOP; r++) {
        unsigned long long m = 0ull;
        for (int i = tid; i < NCAND; i += 128) {
            unsigned long long v = cb[i];
            if (v > m) m = v;
        }
        #pragma unroll
        for (int o = 16; o; o >>= 1) {
            unsigned long long t = __shfl_xor_sync(0xffffffffu, m, o);
            if (t > m) m = t;
        }
        if (lane == 0) wred[warp] = m;
        __syncthreads();
        unsigned long long top = wred[0];
        #pragma unroll
        for (int i = 1; i < 4; i++) if (wred[i] > top) top = wred[i];
        for (int i = tid; i < NCAND; i += 128)
            if (cb[i] == top) cb[i] = 0ull;
        if (tid == 0) mtop[r] = top;
        __syncthreads();
    }

    // exact fp32 rescore of the 48 candidates (one warp per candidate)
    for (int r = warp; r < MTOP; r += 4) {
        unsigned long long pk = mtop[r];
        int key = (int)(0xFFFFFFFFu - (unsigned int)(pk & 0xFFFFFFFFu));
        float4 kv = ((const float4*)(keys + (size_t)key * DDIM))[lane];
        float4 qv = *(const float4*)&qsh[lane * 4];
        float d = kv.x * qv.x + kv.y * qv.y + kv.z * qv.z + kv.w * qv.w;
        #pragma unroll
        for (int o = 16; o; o >>= 1) d += __shfl_xor_sync(0xffffffffu, d, o);
        if (lane == 0) {
            float ex = d * g_scale[key];
            exact[r] = ((unsigned long long)fkey(ex) << 32) |
                       (unsigned long long)(0xFFFFFFFFu - (unsigned int)key);
        }
    }
    __syncthreads();

    // exact top-16 of 48 (warp 0)
    if (warp == 0) {
        unsigned long long va = exact[lane];
        unsigned long long vb = (lane + 32 < MTOP) ? exact[lane + 32] : 0ull;
        for (int r = 0; r < TOPK; r++) {
            unsigned long long m = (va > vb) ? va : vb;
            #pragma unroll
            for (int o = 16; o; o >>= 1) {
                unsigned long long t = __shfl_xor_sync(0xffffffffu, m, o);
                if (t > m) m = t;
            }
            if (va == m) va = 0ull;
            else if (vb == m) vb = 0ull;
            if (lane == 0) {
                float s = funkey((unsigned int)(m >> 32));
                int idx = (int)(0xFFFFFFFFu - (unsigned int)(m & 0xFFFFFFFFu));
                smv[r] = (s >= 0.0f) ? s : 0.0f;   // MIN_SIMILARITY mask
                sidx[r] = idx;
            }
        }
        if (lane == 0) {
            float su = 0.0f;
            #pragma unroll
            for (int r = 0; r < TOPK; r++) su += smv[r];
            su += 1e-8f;
            #pragma unroll
            for (int r = 0; r < TOPK; r++) w[r] = smv[r] / su;
        }
    }
    __syncthreads();

    for (int j = tid; j < HFDIM; j += 128) {
        float a = 0.0f;
        #pragma unroll
        for (int r = 0; r < TOPK; r++)
            a += w[r] * values[(size_t)sidx[r] * HFDIM + j];
        out[(size_t)b * HFDIM + j] = a;
    }
}

// -------- launch --------
extern "C" void kernel_launch(void* const* d_in, const int* in_sizes, int n_in,
                              void* d_out, int out_size) {
    const float* query  = (const float*)d_in[0];
    const float* keys   = (const float*)d_in[1];
    const float* values = (const float*)d_in[2];
    const void*  ts     = d_in[3];
    const int*   gsp    = (n_in > 4) ? (const int*)d_in[4] : nullptr;

    cudaFuncSetAttribute(k_filter,
                         cudaFuncAttributeMaxDynamicSharedMemorySize, SMEM_SZ);

    k_detect<<<1, 32>>>((const unsigned int*)ts);
    k_normq<<<BQ, DDIM>>>(query);
    k_scale<<<(NKEYS * 32 + 255) / 256, 256>>>(keys, ts, gsp, gsp != nullptr);
    k_filter<<<GRID_F, FTHR, SMEM_SZ>>>();
    k_rescore<<<BQ, 128>>>(keys, values, (float*)d_out);
}

// round 7
// speedup vs baseline: 2.9979x; 1.6795x over previous
#include <cuda_runtime.h>
#include <cuda_bf16.h>
#include <math.h>

// Problem constants
#define BQ      1024
#define DDIM    128
#define NKEYS   200000
#define HFDIM   168
#define TOPK    16
#define MTOP    48
#define CHUNK   2048
#define NCHUNKS 98           // 97*2048 + 1344; every 64-key tile full
#define QTILES  8
#define NPAIRS  (QTILES*NCHUNKS)   // 784
#define FTHR    128
#define GRID_F  444          // 3 blocks/SM persistent

// -------- filter kernel SMEM layout (bytes) --------
// [Ks bf16 64x136 | union{Qs bf16 128x136, Sim f32 128x68} | topv | topi | work]
#define OFF_Q     17408
#define OFF_TOPV  52224
#define OFF_TOPI  60928
#define OFF_WORK  69632
#define SMEM_SZ   69648

// -------- scratch --------
__device__ float g_qn[BQ * DDIM];
__device__ __nv_bfloat16 g_qb[BQ * DDIM];
__device__ __nv_bfloat16 g_kbd[(size_t)NKEYS * DDIM];
__device__ float g_scale[NKEYS];
__device__ unsigned long long g_cand[(size_t)BQ * NCHUNKS * TOPK];
__device__ int g_ts64;
__device__ unsigned int g_work;

// -------- helpers --------
__device__ __forceinline__ unsigned int fkey(float f) {
    unsigned int u = __float_as_uint(f);
    return (u & 0x80000000u) ? ~u : (u | 0x80000000u);
}
__device__ __forceinline__ float funkey(unsigned int u) {
    return (u & 0x80000000u) ? __uint_as_float(u ^ 0x80000000u)
                             : __uint_as_float(~u);
}
__device__ __forceinline__ unsigned int su32(const void* p) {
    unsigned int r;
    asm("{.reg .u64 t; cvta.to.shared.u64 t, %1; cvt.u32.u64 %0, t;}"
        : "=r"(r) : "l"(p));
    return r;
}
#define NEG_INF __int_as_float(0xff800000)

// -------- kernel 0: detect ts dtype + reset work counter --------
__global__ void k_detect(const unsigned int* tsw) {
    if (threadIdx.x == 0) {
        int all0 = 1;
        for (int i = 0; i < 64; i++)
            if (tsw[2 * i + 1] != 0u) { all0 = 0; break; }
        g_ts64 = all0;
        g_work = 0u;
    }
}

// -------- kernel 1: normalize queries (fp32 + bf16) --------
__global__ void k_normq(const float* __restrict__ query) {
    int b = blockIdx.x;
    int d = threadIdx.x;
    float v = query[b * DDIM + d];
    float s = v * v;
    #pragma unroll
    for (int o = 16; o; o >>= 1) s += __shfl_xor_sync(0xffffffffu, s, o);
    __shared__ float ws[4];
    if ((d & 31) == 0) ws[d >> 5] = s;
    __syncthreads();
    float tot = ws[0] + ws[1] + ws[2] + ws[3];
    float n = fmaxf(sqrtf(tot), 1e-12f);
    float q = v / n;
    g_qn[b * DDIM + d] = q;
    g_qb[b * DDIM + d] = __float2bfloat16_rn(q);
}

// -------- kernel 2: per-key scale + bf16 decayed keys --------
__global__ void k_scale(const float* __restrict__ keys, const void* ts,
                        const int* gsp, int has_gs) {
    int gw = (blockIdx.x * blockDim.x + threadIdx.x) >> 5;
    int lane = threadIdx.x & 31;
    if (gw >= NKEYS) return;
    float4 a = ((const float4*)(keys + (size_t)gw * DDIM))[lane];
    float s = a.x * a.x + a.y * a.y + a.z * a.z + a.w * a.w;
    #pragma unroll
    for (int o = 16; o; o >>= 1) s += __shfl_xor_sync(0xffffffffu, s, o);
    float sc;
    if (lane == 0) {
        long long t = g_ts64 ? ((const long long*)ts)[gw]
                             : (long long)((const int*)ts)[gw];
        int gs = has_gs ? gsp[0] : 1000;
        float age = (float)(gs - (int)t);
        float dec = powf(0.995f, age);
        float nr = fmaxf(sqrtf(s), 1e-12f);
        sc = dec / nr;
        g_scale[gw] = sc;
    }
    sc = __shfl_sync(0xffffffffu, sc, 0);
    __nv_bfloat162 p0 = __floats2bfloat162_rn(a.x * sc, a.y * sc);
    __nv_bfloat162 p1 = __floats2bfloat162_rn(a.z * sc, a.w * sc);
    uint2 pk = make_uint2(*(unsigned int*)&p0, *(unsigned int*)&p1);
    *(uint2*)&g_kbd[(size_t)gw * DDIM + lane * 4] = pk;
}

// -------- kernel 3: bf16 MMA filter (A-frags in regs) + top-16 --------
__global__ void __launch_bounds__(FTHR, 3)
k_filter() {
    extern __shared__ __align__(16) unsigned char sm[];
    __nv_bfloat16* Ks = (__nv_bfloat16*)sm;             // [64][136]
    __nv_bfloat16* Qs = (__nv_bfloat16*)(sm + OFF_Q);   // [128][136] (union)
    float* Sim  = (float*)(sm + OFF_Q);                 // [128][68]  (union)
    float* topv = (float*)(sm + OFF_TOPV);              // [128][17]
    int*   topi = (int*)(sm + OFF_TOPI);                // [128][17]
    unsigned int* swork = (unsigned int*)(sm + OFF_WORK);

    int tid  = threadIdx.x;
    int warp = tid >> 5;
    int lane = tid & 31;
    int q0 = warp * 32;

    for (;;) {
        __syncthreads();
        if (tid == 0) *swork = atomicAdd(&g_work, 1u);
        __syncthreads();
        unsigned int p = *swork;
        if (p >= NPAIRS) break;
        int chunk = p >> 3;
        int qtile = p & 7;
        int qbase = qtile * 128;
        int c0 = chunk * CHUNK;
        int ntiles = (chunk == NCHUNKS - 1) ? 21 : 32;

        #pragma unroll
        for (int j = 0; j < TOPK; j++) {
            topv[tid * 17 + j] = NEG_INF;
            topi[tid * 17 + j] = 0;
        }
        // load Q tile [128][128] bf16 into union region
        for (int i = tid; i < 128 * 16; i += FTHR) {
            int row = i >> 4, c = i & 15;
            *(uint4*)(Qs + row * 136 + c * 8) =
                *(const uint4*)(g_qb + (qbase + row) * DDIM + c * 8);
        }
        __syncthreads();

        // hoist A fragments into registers (constant across all tiles)
        unsigned int afr[16][4];   // [mi*8+s8][4]
        #pragma unroll
        for (int s8 = 0; s8 < 8; s8++) {
            #pragma unroll
            for (int mi = 0; mi < 2; mi++) {
                int row = q0 + mi * 16 + (lane & 15);
                int col = s8 * 16 + ((lane >> 4) << 3);
                unsigned int ad = su32(Qs + row * 136 + col);
                unsigned int* f = afr[mi * 8 + s8];
                asm volatile(
                    "ldmatrix.sync.aligned.m8n8.x4.shared.b16 {%0,%1,%2,%3}, [%4];"
                    : "=r"(f[0]), "=r"(f[1]), "=r"(f[2]), "=r"(f[3])
                    : "r"(ad));
            }
        }
        __syncthreads();   // A frags read before Sim overwrites union

        for (int t = 0; t < ntiles; t++) {
            int n0g = c0 + t * 64;
            // load K tile [64][128] bf16
            for (int i = tid; i < 64 * 16; i += FTHR) {
                int row = i >> 4, c = i & 15;
                *(uint4*)(Ks + row * 136 + c * 8) =
                    *(const uint4*)(g_kbd + (size_t)(n0g + row) * DDIM + c * 8);
            }
            __syncthreads();

            float acc[2][8][4];
            #pragma unroll
            for (int mi = 0; mi < 2; mi++)
                #pragma unroll
                for (int nt = 0; nt < 8; nt++)
                    #pragma unroll
                    for (int e = 0; e < 4; e++) acc[mi][nt][e] = 0.0f;

            #pragma unroll
            for (int s8 = 0; s8 < 8; s8++) {
                int ds = s8 * 16;
                unsigned int bb[4][4];
                #pragma unroll
                for (int g = 0; g < 4; g++) {
                    int prow = g * 16 + (lane & 7) + ((lane >> 4) << 3);
                    int pcol = ds + (((lane >> 3) & 1) << 3);
                    unsigned int ad = su32(Ks + prow * 136 + pcol);
                    asm volatile(
                        "ldmatrix.sync.aligned.m8n8.x4.shared.b16 {%0,%1,%2,%3}, [%4];"
                        : "=r"(bb[g][0]), "=r"(bb[g][1]), "=r"(bb[g][2]), "=r"(bb[g][3])
                        : "r"(ad));
                }
                #pragma unroll
                for (int mi = 0; mi < 2; mi++) {
                    const unsigned int* a = afr[mi * 8 + s8];
                    #pragma unroll
                    for (int nt = 0; nt < 8; nt++) {
                        unsigned int b0 = bb[nt >> 1][(nt & 1) * 2];
                        unsigned int b1 = bb[nt >> 1][(nt & 1) * 2 + 1];
                        asm volatile(
                            "mma.sync.aligned.m16n8k16.row.col.f32.bf16.bf16.f32 "
                            "{%0,%1,%2,%3}, {%4,%5,%6,%7}, {%8,%9}, {%0,%1,%2,%3};"
                            : "+f"(acc[mi][nt][0]), "+f"(acc[mi][nt][1]),
                              "+f"(acc[mi][nt][2]), "+f"(acc[mi][nt][3])
                            : "r"(a[0]), "r"(a[1]), "r"(a[2]), "r"(a[3]),
                              "r"(b0), "r"(b1));
                    }
                }
            }
            __syncthreads();   // prior scan reads done before Sim store
            #pragma unroll
            for (int mi = 0; mi < 2; mi++)
                #pragma unroll
                for (int nt = 0; nt < 8; nt++) {
                    int row = q0 + mi * 16 + (lane >> 2);
                    int col = nt * 8 + (lane & 3) * 2;
                    *(float2*)&Sim[row * 68 + col] =
                        make_float2(acc[mi][nt][0], acc[mi][nt][1]);
                    *(float2*)&Sim[(row + 8) * 68 + col] =
                        make_float2(acc[mi][nt][2], acc[mi][nt][3]);
                }
            __syncthreads();

            // max-prefilter scan: thread owns query tid
            {
                float thr = topv[tid * 17 + TOPK - 1];
                const float4* row4 = (const float4*)&Sim[tid * 68];
                float m = NEG_INF;
                #pragma unroll
                for (int j = 0; j < 16; j++) {
                    float4 v = row4[j];
                    m = fmaxf(m, fmaxf(fmaxf(v.x, v.y), fmaxf(v.z, v.w)));
                }
                if (m > thr) {
                    const float* row = &Sim[tid * 68];
                    for (int j = 0; j < 64; j++) {
                        float vv = row[j];
                        if (vv > thr) {
                            int kidx = n0g + j;
                            int pos = TOPK - 1;
                            while (pos > 0 && topv[tid * 17 + pos - 1] < vv) {
                                topv[tid * 17 + pos] = topv[tid * 17 + pos - 1];
                                topi[tid * 17 + pos] = topi[tid * 17 + pos - 1];
                                pos--;
                            }
                            topv[tid * 17 + pos] = vv;
                            topi[tid * 17 + pos] = kidx;
                            thr = topv[tid * 17 + TOPK - 1];
                        }
                    }
                }
            }
            __syncthreads();   // scan done before next K/Sim overwrite
        }

        {
            int b = qbase + tid;
            unsigned long long* dst = &g_cand[((size_t)b * NCHUNKS + chunk) * TOPK];
            #pragma unroll
            for (int j = 0; j < TOPK; j++) {
                unsigned long long hv =
                    (unsigned long long)fkey(topv[tid * 17 + j]) << 32;
                dst[j] = hv | (unsigned long long)(0xFFFFFFFFu -
                                (unsigned int)topi[tid * 17 + j]);
            }
        }
    }
}

// -------- kernel 4: merge approx top-48, exact rescore, output --------
#define NCAND (NCHUNKS * TOPK)   // 1568

__global__ void __launch_bounds__(128)
k_rescore(const float* __restrict__ keys, const float* __restrict__ values,
          float* __restrict__ out) {
    __shared__ unsigned long long cb[NCAND];
    __shared__ unsigned long long wred[4];
    __shared__ unsigned long long mtop[MTOP];
    __shared__ unsigned long long exact[MTOP];
    __shared__ float qsh[DDIM];
    __shared__ float smv[TOPK];
    __shared__ int   sidx[TOPK];
    __shared__ float w[TOPK];

    int b = blockIdx.x, tid = threadIdx.x;
    int lane = tid & 31, warp = tid >> 5;

    const unsigned long long* src = &g_cand[(size_t)b * NCAND];
    for (int i = tid; i < NCAND; i += 128) cb[i] = src[i];
    qsh[tid] = g_qn[b * DDIM + tid];
    __syncthreads();

    for (int r = 0; r < MTOP; r++) {
        unsigned long long m = 0ull;
        for (int i = tid; i < NCAND; i += 128) {
            unsigned long long v = cb[i];
            if (v > m) m = v;
        }
        #pragma unroll
        for (int o = 16; o; o >>= 1) {
            unsigned long long t = __shfl_xor_sync(0xffffffffu, m, o);
            if (t > m) m = t;
        }
        if (lane == 0) wred[warp] = m;
        __syncthreads();
        unsigned long long top = wred[0];
        #pragma unroll
        for (int i = 1; i < 4; i++) if (wred[i] > top) top = wred[i];
        for (int i = tid; i < NCAND; i += 128)
            if (cb[i] == top) cb[i] = 0ull;
        if (tid == 0) mtop[r] = top;
        __syncthreads();
    }

    for (int r = warp; r < MTOP; r += 4) {
        unsigned long long pk = mtop[r];
        int key = (int)(0xFFFFFFFFu - (unsigned int)(pk & 0xFFFFFFFFu));
        float4 kv = ((const float4*)(keys + (size_t)key * DDIM))[lane];
        float4 qv = *(const float4*)&qsh[lane * 4];
        float d = kv.x * qv.x + kv.y * qv.y + kv.z * qv.z + kv.w * qv.w;
        #pragma unroll
        for (int o = 16; o; o >>= 1) d += __shfl_xor_sync(0xffffffffu, d, o);
        if (lane == 0) {
            float ex = d * g_scale[key];
            exact[r] = ((unsigned long long)fkey(ex) << 32) |
                       (unsigned long long)(0xFFFFFFFFu - (unsigned int)key);
        }
    }
    __syncthreads();

    if (warp == 0) {
        unsigned long long va = exact[lane];
        unsigned long long vb = (lane + 32 < MTOP) ? exact[lane + 32] : 0ull;
        for (int r = 0; r < TOPK; r++) {
            unsigned long long m = (va > vb) ? va : vb;
            #pragma unroll
            for (int o = 16; o; o >>= 1) {
                unsigned long long t = __shfl_xor_sync(0xffffffffu, m, o);
                if (t > m) m = t;
            }
            if (va == m) va = 0ull;
            else if (vb == m) vb = 0ull;
            if (lane == 0) {
                float s = funkey((unsigned int)(m >> 32));
                int idx = (int)(0xFFFFFFFFu - (unsigned int)(m & 0xFFFFFFFFu));
                smv[r] = (s >= 0.0f) ? s : 0.0f;
                sidx[r] = idx;
            }
        }
        if (lane == 0) {
            float su = 0.0f;
            #pragma unroll
            for (int r = 0; r < TOPK; r++) su += smv[r];
            su += 1e-8f;
            #pragma unroll
            for (int r = 0; r < TOPK; r++) w[r] = smv[r] / su;
        }
    }
    __syncthreads();

    for (int j = tid; j < HFDIM; j += 128) {
        float a = 0.0f;
        #pragma unroll
        for (int r = 0; r < TOPK; r++)
            a += w[r] * values[(size_t)sidx[r] * HFDIM + j];
        out[(size_t)b * HFDIM + j] = a;
    }
}

// -------- launch --------
extern "C" void kernel_launch(void* const* d_in, const int* in_sizes, int n_in,
                              void* d_out, int out_size) {
    const float* query  = (const float*)d_in[0];
    const float* keys   = (const float*)d_in[1];
    const float* values = (const float*)d_in[2];
    const void*  ts     = d_in[3];
    const int*   gsp    = (n_in > 4) ? (const int*)d_in[4] : nullptr;

    cudaFuncSetAttribute(k_filter,
                         cudaFuncAttributeMaxDynamicSharedMemorySize, SMEM_SZ);

    k_detect<<<1, 32>>>((const unsigned int*)ts);
    k_normq<<<BQ, DDIM>>>(query);
    k_scale<<<(NKEYS * 32 + 255) / 256, 256>>>(keys, ts, gsp, gsp != nullptr);
    k_filter<<<GRID_F, FTHR, SMEM_SZ>>>();
    k_rescore<<<BQ, 128>>>(keys, values, (float*)d_out);
}

// round 8
// speedup vs baseline: 3.5028x; 1.1684x over previous
#include <cuda_runtime.h>
#include <cuda_bf16.h>
#include <math.h>

// Problem constants
#define BQ      1024
#define DDIM    128
#define NKEYS   200000
#define HFDIM   168
#define TOPK    16
#define MTOP    48
#define CHUNK   2048
#define NCHUNKS 98           // 97*2048 + 1344; every 64-key tile full
#define QTILES  8
#define NPAIRS  (QTILES*NCHUNKS)   // 784
#define FTHR    128
#define GRID_F  444          // 3 blocks/SM persistent

// -------- filter kernel SMEM layout (bytes) --------
// [Ks bf16 64x136 | union{Qs bf16 128x136, Sim f32 128x68} | topv | topi | rowmax | work]
#define OFF_Q     17408
#define OFF_TOPV  52224
#define OFF_TOPI  60928
#define OFF_RMAX  69632
#define OFF_WORK  70144
#define SMEM_SZ   70160

// -------- scratch --------
__device__ float g_qn[BQ * DDIM];
__device__ __nv_bfloat16 g_qb[BQ * DDIM];
__device__ __nv_bfloat16 g_kbd[(size_t)NKEYS * DDIM];
__device__ float g_scale[NKEYS];
__device__ unsigned long long g_cand[(size_t)BQ * NCHUNKS * TOPK];
__device__ int g_ts64;
__device__ unsigned int g_work;

// -------- helpers --------
__device__ __forceinline__ unsigned int fkey(float f) {
    unsigned int u = __float_as_uint(f);
    return (u & 0x80000000u) ? ~u : (u | 0x80000000u);
}
__device__ __forceinline__ float funkey(unsigned int u) {
    return (u & 0x80000000u) ? __uint_as_float(u ^ 0x80000000u)
                             : __uint_as_float(~u);
}
__device__ __forceinline__ unsigned int su32(const void* p) {
    unsigned int r;
    asm("{.reg .u64 t; cvta.to.shared.u64 t, %1; cvt.u32.u64 %0, t;}"
        : "=r"(r) : "l"(p));
    return r;
}
#define NEG_INF __int_as_float(0xff800000)

// -------- kernel 0: detect ts dtype + reset work counter --------
__global__ void k_detect(const unsigned int* tsw) {
    if (threadIdx.x == 0) {
        int all0 = 1;
        for (int i = 0; i < 64; i++)
            if (tsw[2 * i + 1] != 0u) { all0 = 0; break; }
        g_ts64 = all0;
        g_work = 0u;
    }
}

// -------- kernel 1: normalize queries (fp32 + bf16) --------
__global__ void k_normq(const float* __restrict__ query) {
    int b = blockIdx.x;
    int d = threadIdx.x;
    float v = query[b * DDIM + d];
    float s = v * v;
    #pragma unroll
    for (int o = 16; o; o >>= 1) s += __shfl_xor_sync(0xffffffffu, s, o);
    __shared__ float ws[4];
    if ((d & 31) == 0) ws[d >> 5] = s;
    __syncthreads();
    float tot = ws[0] + ws[1] + ws[2] + ws[3];
    float n = fmaxf(sqrtf(tot), 1e-12f);
    float q = v / n;
    g_qn[b * DDIM + d] = q;
    g_qb[b * DDIM + d] = __float2bfloat16_rn(q);
}

// -------- kernel 2: per-key scale + bf16 decayed keys --------
__global__ void k_scale(const float* __restrict__ keys, const void* ts,
                        const int* gsp, int has_gs) {
    int gw = (blockIdx.x * blockDim.x + threadIdx.x) >> 5;
    int lane = threadIdx.x & 31;
    if (gw >= NKEYS) return;
    float4 a = ((const float4*)(keys + (size_t)gw * DDIM))[lane];
    float s = a.x * a.x + a.y * a.y + a.z * a.z + a.w * a.w;
    #pragma unroll
    for (int o = 16; o; o >>= 1) s += __shfl_xor_sync(0xffffffffu, s, o);
    float sc;
    if (lane == 0) {
        long long t = g_ts64 ? ((const long long*)ts)[gw]
                             : (long long)((const int*)ts)[gw];
        int gs = has_gs ? gsp[0] : 1000;
        float age = (float)(gs - (int)t);
        float dec = powf(0.995f, age);
        float nr = fmaxf(sqrtf(s), 1e-12f);
        sc = dec / nr;
        g_scale[gw] = sc;
    }
    sc = __shfl_sync(0xffffffffu, sc, 0);
    __nv_bfloat162 p0 = __floats2bfloat162_rn(a.x * sc, a.y * sc);
    __nv_bfloat162 p1 = __floats2bfloat162_rn(a.z * sc, a.w * sc);
    uint2 pk = make_uint2(*(unsigned int*)&p0, *(unsigned int*)&p1);
    *(uint2*)&g_kbd[(size_t)gw * DDIM + lane * 4] = pk;
}

// -------- kernel 3: bf16 MMA filter, register rowmax, lazy scan --------
__global__ void __launch_bounds__(FTHR, 3)
k_filter() {
    extern __shared__ __align__(16) unsigned char sm[];
    __nv_bfloat16* Ks = (__nv_bfloat16*)sm;             // [64][136]
    __nv_bfloat16* Qs = (__nv_bfloat16*)(sm + OFF_Q);   // [128][136] (union)
    float* Sim    = (float*)(sm + OFF_Q);               // [128][68]  (union)
    float* topv   = (float*)(sm + OFF_TOPV);            // [128][17]
    int*   topi   = (int*)(sm + OFF_TOPI);              // [128][17]
    float* rowmax = (float*)(sm + OFF_RMAX);            // [128]
    unsigned int* swork = (unsigned int*)(sm + OFF_WORK);

    int tid  = threadIdx.x;
    int warp = tid >> 5;
    int lane = tid & 31;
    int q0 = warp * 32;

    for (;;) {
        __syncthreads();
        if (tid == 0) *swork = atomicAdd(&g_work, 1u);
        __syncthreads();
        unsigned int p = *swork;
        if (p >= NPAIRS) break;
        int chunk = p >> 3;
        int qtile = p & 7;
        int qbase = qtile * 128;
        int c0 = chunk * CHUNK;
        int ntiles = (chunk == NCHUNKS - 1) ? 21 : 32;

        #pragma unroll
        for (int j = 0; j < TOPK; j++) {
            topv[tid * 17 + j] = NEG_INF;
            topi[tid * 17 + j] = 0;
        }
        // load Q tile [128][128] bf16 into union region
        for (int i = tid; i < 128 * 16; i += FTHR) {
            int row = i >> 4, c = i & 15;
            *(uint4*)(Qs + row * 136 + c * 8) =
                *(const uint4*)(g_qb + (qbase + row) * DDIM + c * 8);
        }
        __syncthreads();

        // hoist A fragments (constant across all tiles of this work item)
        unsigned int afr[16][4];
        #pragma unroll
        for (int s8 = 0; s8 < 8; s8++) {
            #pragma unroll
            for (int mi = 0; mi < 2; mi++) {
                int row = q0 + mi * 16 + (lane & 15);
                int col = s8 * 16 + ((lane >> 4) << 3);
                unsigned int ad = su32(Qs + row * 136 + col);
                unsigned int* f = afr[mi * 8 + s8];
                asm volatile(
                    "ldmatrix.sync.aligned.m8n8.x4.shared.b16 {%0,%1,%2,%3}, [%4];"
                    : "=r"(f[0]), "=r"(f[1]), "=r"(f[2]), "=r"(f[3])
                    : "r"(ad));
            }
        }
        __syncthreads();   // A frags read before Sim overwrites union

        for (int t = 0; t < ntiles; t++) {
            int n0g = c0 + t * 64;
            // stage K tile [64][128] bf16
            for (int i = tid; i < 64 * 16; i += FTHR) {
                int row = i >> 4, c = i & 15;
                *(uint4*)(Ks + row * 136 + c * 8) =
                    *(const uint4*)(g_kbd + (size_t)(n0g + row) * DDIM + c * 8);
            }
            __syncthreads();

            float acc[2][8][4];
            #pragma unroll
            for (int mi = 0; mi < 2; mi++)
                #pragma unroll
                for (int nt = 0; nt < 8; nt++)
                    #pragma unroll
                    for (int e = 0; e < 4; e++) acc[mi][nt][e] = 0.0f;

            #pragma unroll
            for (int s8 = 0; s8 < 8; s8++) {
                int ds = s8 * 16;
                unsigned int bb[4][4];
                #pragma unroll
                for (int g = 0; g < 4; g++) {
                    int prow = g * 16 + (lane & 7) + ((lane >> 4) << 3);
                    int pcol = ds + (((lane >> 3) & 1) << 3);
                    unsigned int ad = su32(Ks + prow * 136 + pcol);
                    asm volatile(
                        "ldmatrix.sync.aligned.m8n8.x4.shared.b16 {%0,%1,%2,%3}, [%4];"
                        : "=r"(bb[g][0]), "=r"(bb[g][1]), "=r"(bb[g][2]), "=r"(bb[g][3])
                        : "r"(ad));
                }
                #pragma unroll
                for (int mi = 0; mi < 2; mi++) {
                    const unsigned int* a = afr[mi * 8 + s8];
                    #pragma unroll
                    for (int nt = 0; nt < 8; nt++) {
                        unsigned int b0 = bb[nt >> 1][(nt & 1) * 2];
                        unsigned int b1 = bb[nt >> 1][(nt & 1) * 2 + 1];
                        asm volatile(
                            "mma.sync.aligned.m16n8k16.row.col.f32.bf16.bf16.f32 "
                            "{%0,%1,%2,%3}, {%4,%5,%6,%7}, {%8,%9}, {%0,%1,%2,%3};"
                            : "+f"(acc[mi][nt][0]), "+f"(acc[mi][nt][1]),
                              "+f"(acc[mi][nt][2]), "+f"(acc[mi][nt][3])
                            : "r"(a[0]), "r"(a[1]), "r"(a[2]), "r"(a[3]),
                              "r"(b0), "r"(b1));
                    }
                }
            }
            __syncthreads();   // all warps done with Ks before next staging

            // register rowmax: thread covers rows r0, r0+8 (mi=0) and +16,+24 (mi=1)
            float mx[4];
            #pragma unroll
            for (int mi = 0; mi < 2; mi++) {
                float mlo = NEG_INF, mhi = NEG_INF;
                #pragma unroll
                for (int nt = 0; nt < 8; nt++) {
                    mlo = fmaxf(mlo, fmaxf(acc[mi][nt][0], acc[mi][nt][1]));
                    mhi = fmaxf(mhi, fmaxf(acc[mi][nt][2], acc[mi][nt][3]));
                }
                mlo = fmaxf(mlo, __shfl_xor_sync(0xffffffffu, mlo, 1));
                mlo = fmaxf(mlo, __shfl_xor_sync(0xffffffffu, mlo, 2));
                mhi = fmaxf(mhi, __shfl_xor_sync(0xffffffffu, mhi, 1));
                mhi = fmaxf(mhi, __shfl_xor_sync(0xffffffffu, mhi, 2));
                mx[mi * 2] = mlo;
                mx[mi * 2 + 1] = mhi;
            }
            int need = 0;
            if ((lane & 3) == 0) {
                int r0 = q0 + (lane >> 2);
                rowmax[r0]      = mx[0];
                rowmax[r0 + 8]  = mx[1];
                rowmax[r0 + 16] = mx[2];
                rowmax[r0 + 24] = mx[3];
                need = (mx[0] > topv[r0 * 17 + 15]) |
                       (mx[1] > topv[(r0 + 8) * 17 + 15]) |
                       (mx[2] > topv[(r0 + 16) * 17 + 15]) |
                       (mx[3] > topv[(r0 + 24) * 17 + 15]);
            }
            if (__any_sync(0xffffffffu, need)) {
                // store Sim (warp-local rows) and scan flagged rows
                __syncwarp();
                #pragma unroll
                for (int mi = 0; mi < 2; mi++)
                    #pragma unroll
                    for (int nt = 0; nt < 8; nt++) {
                        int row = q0 + mi * 16 + (lane >> 2);
                        int col = nt * 8 + (lane & 3) * 2;
                        *(float2*)&Sim[row * 68 + col] =
                            make_float2(acc[mi][nt][0], acc[mi][nt][1]);
                        *(float2*)&Sim[(row + 8) * 68 + col] =
                            make_float2(acc[mi][nt][2], acc[mi][nt][3]);
                    }
                __syncwarp();
                float thr = topv[tid * 17 + TOPK - 1];
                if (rowmax[tid] > thr) {
                    const float4* row4 = (const float4*)&Sim[tid * 68];
                    for (int j4 = 0; j4 < 16; j4++) {
                        float4 v = row4[j4];
                        if (fmaxf(fmaxf(v.x, v.y), fmaxf(v.z, v.w)) > thr) {
                            #pragma unroll
                            for (int e = 0; e < 4; e++) {
                                float vv = (e == 0) ? v.x : (e == 1) ? v.y
                                         : (e == 2) ? v.z : v.w;
                                if (vv > thr) {
                                    int kidx = n0g + j4 * 4 + e;
                                    int pos = TOPK - 1;
                                    while (pos > 0 && topv[tid * 17 + pos - 1] < vv) {
                                        topv[tid * 17 + pos] = topv[tid * 17 + pos - 1];
                                        topi[tid * 17 + pos] = topi[tid * 17 + pos - 1];
                                        pos--;
                                    }
                                    topv[tid * 17 + pos] = vv;
                                    topi[tid * 17 + pos] = kidx;
                                    thr = topv[tid * 17 + TOPK - 1];
                                }
                            }
                        }
                    }
                }
                __syncwarp();  // scans done before next tile's Sim overwrite
            }
        }
        __syncthreads();

        {
            int b = qbase + tid;
            unsigned long long* dst = &g_cand[((size_t)b * NCHUNKS + chunk) * TOPK];
            #pragma unroll
            for (int j = 0; j < TOPK; j++) {
                unsigned long long hv =
                    (unsigned long long)fkey(topv[tid * 17 + j]) << 32;
                dst[j] = hv | (unsigned long long)(0xFFFFFFFFu -
                                (unsigned int)topi[tid * 17 + j]);
            }
        }
    }
}

// -------- kernel 4: merge approx top-48, exact rescore, output --------
#define NCAND (NCHUNKS * TOPK)   // 1568

__global__ void __launch_bounds__(128)
k_rescore(const float* __restrict__ keys, const float* __restrict__ values,
          float* __restrict__ out) {
    __shared__ unsigned long long cb[NCAND];
    __shared__ unsigned long long wred[4];
    __shared__ unsigned long long mtop[MTOP];
    __shared__ unsigned long long exact[MTOP];
    __shared__ float qsh[DDIM];
    __shared__ float smv[TOPK];
    __shared__ int   sidx[TOPK];
    __shared__ float w[TOPK];

    int b = blockIdx.x, tid = threadIdx.x;
    int lane = tid & 31, warp = tid >> 5;

    const unsigned long long* src = &g_cand[(size_t)b * NCAND];
    for (int i = tid; i < NCAND; i += 128) cb[i] = src[i];
    qsh[tid] = g_qn[b * DDIM + tid];
    __syncthreads();

    for (int r = 0; r < MTOP; r++) {
        unsigned long long m = 0ull;
        for (int i = tid; i < NCAND; i += 128) {
            unsigned long long v = cb[i];
            if (v > m) m = v;
        }
        #pragma unroll
        for (int o = 16; o; o >>= 1) {
            unsigned long long t = __shfl_xor_sync(0xffffffffu, m, o);
            if (t > m) m = t;
        }
        if (lane == 0) wred[warp] = m;
        __syncthreads();
        unsigned long long top = wred[0];
        #pragma unroll
        for (int i = 1; i < 4; i++) if (wred[i] > top) top = wred[i];
        for (int i = tid; i < NCAND; i += 128)
            if (cb[i] == top) cb[i] = 0ull;
        if (tid == 0) mtop[r] = top;
        __syncthreads();
    }

    for (int r = warp; r < MTOP; r += 4) {
        unsigned long long pk = mtop[r];
        int key = (int)(0xFFFFFFFFu - (unsigned int)(pk & 0xFFFFFFFFu));
        float4 kv = ((const float4*)(keys + (size_t)key * DDIM))[lane];
        float4 qv = *(const float4*)&qsh[lane * 4];
        float d = kv.x * qv.x + kv.y * qv.y + kv.z * qv.z + kv.w * qv.w;
        #pragma unroll
        for (int o = 16; o; o >>= 1) d += __shfl_xor_sync(0xffffffffu, d, o);
        if (lane == 0) {
            float ex = d * g_scale[key];
            exact[r] = ((unsigned long long)fkey(ex) << 32) |
                       (unsigned long long)(0xFFFFFFFFu - (unsigned int)key);
        }
    }
    __syncthreads();

    if (warp == 0) {
        unsigned long long va = exact[lane];
        unsigned long long vb = (lane + 32 < MTOP) ? exact[lane + 32] : 0ull;
        for (int r = 0; r < TOPK; r++) {
            unsigned long long m = (va > vb) ? va : vb;
            #pragma unroll
            for (int o = 16; o; o >>= 1) {
                unsigned long long t = __shfl_xor_sync(0xffffffffu, m, o);
                if (t > m) m = t;
            }
            if (va == m) va = 0ull;
            else if (vb == m) vb = 0ull;
            if (lane == 0) {
                float s = funkey((unsigned int)(m >> 32));
                int idx = (int)(0xFFFFFFFFu - (unsigned int)(m & 0xFFFFFFFFu));
                smv[r] = (s >= 0.0f) ? s : 0.0f;
                sidx[r] = idx;
            }
        }
        if (lane == 0) {
            float su = 0.0f;
            #pragma unroll
            for (int r = 0; r < TOPK; r++) su += smv[r];
            su += 1e-8f;
            #pragma unroll
            for (int r = 0; r < TOPK; r++) w[r] = smv[r] / su;
        }
    }
    __syncthreads();

    for (int j = tid; j < HFDIM; j += 128) {
        float a = 0.0f;
        #pragma unroll
        for (int r = 0; r < TOPK; r++)
            a += w[r] * values[(size_t)sidx[r] * HFDIM + j];
        out[(size_t)b * HFDIM + j] = a;
    }
}

// -------- launch --------
extern "C" void kernel_launch(void* const* d_in, const int* in_sizes, int n_in,
                              void* d_out, int out_size) {
    const float* query  = (const float*)d_in[0];
    const float* keys   = (const float*)d_in[1];
    const float* values = (const float*)d_in[2];
    const void*  ts     = d_in[3];
    const int*   gsp    = (n_in > 4) ? (const int*)d_in[4] : nullptr;

    cudaFuncSetAttribute(k_filter,
                         cudaFuncAttributeMaxDynamicSharedMemorySize, SMEM_SZ);

    k_detect<<<1, 32>>>((const unsigned int*)ts);
    k_normq<<<BQ, DDIM>>>(query);
    k_scale<<<(NKEYS * 32 + 255) / 256, 256>>>(keys, ts, gsp, gsp != nullptr);
    k_filter<<<GRID_F, FTHR, SMEM_SZ>>>();
    k_rescore<<<BQ, 128>>>(keys, values, (float*)d_out);
}

// round 9
// speedup vs baseline: 3.5073x; 1.0013x over previous
#include <cuda_runtime.h>
#include <cuda_bf16.h>
#include <math.h>

// Problem constants
#define BQ      1024
#define DDIM    128
#define NKEYS   200000
#define HFDIM   168
#define TOPK    16
#define MTOP    64
#define CHUNK   2048
#define NCHUNKS 98           // 97*2048 + 1344; every 64-key tile full
#define QTILES  8
#define NPAIRS  (QTILES*NCHUNKS)   // 784
#define FTHR    128
#define GRID_F  444          // 3 blocks/SM persistent

// -------- filter kernel SMEM layout (bytes) --------
// [Ks bf16 2x64x136 (34816, unioned with Qs 128x136) | Sim bf16 128x72 |
//  topv f32 128x17 | topi 128x17 | rowmax 128 | work]
#define KBUF_B    17408
#define OFF_SIM   34816
#define OFF_TOPV  53248
#define OFF_TOPI  61952
#define OFF_RMAX  70656
#define OFF_WORK  71168
#define SMEM_SZ   71184

// -------- scratch --------
__device__ float g_qn[BQ * DDIM];
__device__ __nv_bfloat16 g_qb[BQ * DDIM];
__device__ __nv_bfloat16 g_kbd[(size_t)NKEYS * DDIM];
__device__ float g_scale[NKEYS];
__device__ unsigned long long g_cand[(size_t)BQ * NCHUNKS * TOPK];
__device__ int g_ts64;
__device__ unsigned int g_work;

// -------- helpers --------
__device__ __forceinline__ unsigned int fkey(float f) {
    unsigned int u = __float_as_uint(f);
    return (u & 0x80000000u) ? ~u : (u | 0x80000000u);
}
__device__ __forceinline__ float funkey(unsigned int u) {
    return (u & 0x80000000u) ? __uint_as_float(u ^ 0x80000000u)
                             : __uint_as_float(~u);
}
__device__ __forceinline__ unsigned int su32(const void* p) {
    unsigned int r;
    asm("{.reg .u64 t; cvta.to.shared.u64 t, %1; cvt.u32.u64 %0, t;}"
        : "=r"(r) : "l"(p));
    return r;
}
__device__ __forceinline__ void cp16(unsigned int dst, const void* src) {
    asm volatile("cp.async.cg.shared.global [%0], [%1], 16;"
                 :: "r"(dst), "l"(src));
}
#define CP_COMMIT() asm volatile("cp.async.commit_group;")
#define CP_WAIT0()  asm volatile("cp.async.wait_group 0;")
#define NEG_INF __int_as_float(0xff800000)

// -------- kernel 0: detect ts dtype + reset work counter --------
__global__ void k_detect(const unsigned int* tsw) {
    if (threadIdx.x == 0) {
        int all0 = 1;
        for (int i = 0; i < 64; i++)
            if (tsw[2 * i + 1] != 0u) { all0 = 0; break; }
        g_ts64 = all0;
        g_work = 0u;
    }
}

// -------- kernel 1: normalize queries (fp32 + bf16) --------
__global__ void k_normq(const float* __restrict__ query) {
    int b = blockIdx.x;
    int d = threadIdx.x;
    float v = query[b * DDIM + d];
    float s = v * v;
    #pragma unroll
    for (int o = 16; o; o >>= 1) s += __shfl_xor_sync(0xffffffffu, s, o);
    __shared__ float ws[4];
    if ((d & 31) == 0) ws[d >> 5] = s;
    __syncthreads();
    float tot = ws[0] + ws[1] + ws[2] + ws[3];
    float n = fmaxf(sqrtf(tot), 1e-12f);
    float q = v / n;
    g_qn[b * DDIM + d] = q;
    g_qb[b * DDIM + d] = __float2bfloat16_rn(q);
}

// -------- kernel 2: per-key scale + bf16 decayed keys --------
__global__ void k_scale(const float* __restrict__ keys, const void* ts,
                        const int* gsp, int has_gs) {
    int gw = (blockIdx.x * blockDim.x + threadIdx.x) >> 5;
    int lane = threadIdx.x & 31;
    if (gw >= NKEYS) return;
    float4 a = ((const float4*)(keys + (size_t)gw * DDIM))[lane];
    float s = a.x * a.x + a.y * a.y + a.z * a.z + a.w * a.w;
    #pragma unroll
    for (int o = 16; o; o >>= 1) s += __shfl_xor_sync(0xffffffffu, s, o);
    float sc;
    if (lane == 0) {
        long long t = g_ts64 ? ((const long long*)ts)[gw]
                             : (long long)((const int*)ts)[gw];
        int gs = has_gs ? gsp[0] : 1000;
        float age = (float)(gs - (int)t);
        float dec = powf(0.995f, age);
        float nr = fmaxf(sqrtf(s), 1e-12f);
        sc = dec / nr;
        g_scale[gw] = sc;
    }
    sc = __shfl_sync(0xffffffffu, sc, 0);
    __nv_bfloat162 p0 = __floats2bfloat162_rn(a.x * sc, a.y * sc);
    __nv_bfloat162 p1 = __floats2bfloat162_rn(a.z * sc, a.w * sc);
    uint2 pk = make_uint2(*(unsigned int*)&p0, *(unsigned int*)&p1);
    *(uint2*)&g_kbd[(size_t)gw * DDIM + lane * 4] = pk;
}

// -------- kernel 3: bf16 MMA filter, cp.async pipeline, lazy scan --------
__global__ void __launch_bounds__(FTHR, 3)
k_filter() {
    extern __shared__ __align__(16) unsigned char sm[];
    __nv_bfloat16* Ks = (__nv_bfloat16*)sm;             // [2][64][136]
    __nv_bfloat16* Qs = (__nv_bfloat16*)sm;             // [128][136] (prologue union)
    __nv_bfloat16* Sim = (__nv_bfloat16*)(sm + OFF_SIM);// [128][72]
    float* topv   = (float*)(sm + OFF_TOPV);            // [128][17]
    int*   topi   = (int*)(sm + OFF_TOPI);              // [128][17]
    float* rowmax = (float*)(sm + OFF_RMAX);            // [128]
    unsigned int* swork = (unsigned int*)(sm + OFF_WORK);

    unsigned int ks_base = su32(Ks);
    int tid  = threadIdx.x;
    int warp = tid >> 5;
    int lane = tid & 31;
    int q0 = warp * 32;
    int qr = lane >> 2;

    for (;;) {
        __syncthreads();
        if (tid == 0) *swork = atomicAdd(&g_work, 1u);
        __syncthreads();
        unsigned int p = *swork;
        if (p >= NPAIRS) break;
        int chunk = p >> 3;
        int qtile = p & 7;
        int qbase = qtile * 128;
        int c0 = chunk * CHUNK;
        int ntiles = (chunk == NCHUNKS - 1) ? 21 : 32;

        #pragma unroll
        for (int j = 0; j < TOPK; j++) {
            topv[tid * 17 + j] = NEG_INF;
            topi[tid * 17 + j] = 0;
        }
        // prologue: stage Q [128][128] bf16 through the K double-buffer region
        for (int i = tid; i < 128 * 16; i += FTHR) {
            int row = i >> 4, c = i & 15;
            *(uint4*)(Qs + row * 136 + c * 8) =
                *(const uint4*)(g_qb + (qbase + row) * DDIM + c * 8);
        }
        __syncthreads();
        unsigned int afr[16][4];
        #pragma unroll
        for (int s8 = 0; s8 < 8; s8++) {
            #pragma unroll
            for (int mi = 0; mi < 2; mi++) {
                int row = q0 + mi * 16 + (lane & 15);
                int col = s8 * 16 + ((lane >> 4) << 3);
                unsigned int ad = su32(Qs + row * 136 + col);
                unsigned int* f = afr[mi * 8 + s8];
                asm volatile(
                    "ldmatrix.sync.aligned.m8n8.x4.shared.b16 {%0,%1,%2,%3}, [%4];"
                    : "=r"(f[0]), "=r"(f[1]), "=r"(f[2]), "=r"(f[3])
                    : "r"(ad));
            }
        }
        __syncthreads();   // A frags read before K tile 0 overwrites

        // issue K tile 0 into buffer 0
        {
            int n0g = c0;
            #pragma unroll
            for (int it = 0; it < 8; it++) {
                int i = tid + it * FTHR;
                int row = i >> 4, c = i & 15;
                cp16(ks_base + row * 272 + c * 16,
                     g_kbd + (size_t)(n0g + row) * DDIM + c * 8);
            }
            CP_COMMIT();
        }

        for (int t = 0; t < ntiles; t++) {
            int n0g = c0 + t * 64;
            unsigned int kb_off = (t & 1) * KBUF_B;
            CP_WAIT0();
            __syncthreads();   // tile t ready; all warps done with tile t-1

            // prefetch tile t+1 into the other buffer
            if (t + 1 < ntiles) {
                int n1 = c0 + (t + 1) * 64;
                unsigned int ob = ((t + 1) & 1) * KBUF_B;
                #pragma unroll
                for (int it = 0; it < 8; it++) {
                    int i = tid + it * FTHR;
                    int row = i >> 4, c = i & 15;
                    cp16(ks_base + ob + row * 272 + c * 16,
                         g_kbd + (size_t)(n1 + row) * DDIM + c * 8);
                }
            }
            CP_COMMIT();

            float acc[2][8][4];
            #pragma unroll
            for (int mi = 0; mi < 2; mi++)
                #pragma unroll
                for (int nt = 0; nt < 8; nt++)
                    #pragma unroll
                    for (int e = 0; e < 4; e++) acc[mi][nt][e] = 0.0f;

            #pragma unroll
            for (int s8 = 0; s8 < 8; s8++) {
                int ds = s8 * 16;
                unsigned int bb[4][4];
                #pragma unroll
                for (int g = 0; g < 4; g++) {
                    int prow = g * 16 + (lane & 7) + ((lane >> 4) << 3);
                    int pcol = ds + (((lane >> 3) & 1) << 3);
                    unsigned int ad = ks_base + kb_off + prow * 272 + pcol * 2;
                    asm volatile(
                        "ldmatrix.sync.aligned.m8n8.x4.shared.b16 {%0,%1,%2,%3}, [%4];"
                        : "=r"(bb[g][0]), "=r"(bb[g][1]), "=r"(bb[g][2]), "=r"(bb[g][3])
                        : "r"(ad));
                }
                #pragma unroll
                for (int mi = 0; mi < 2; mi++) {
                    const unsigned int* a = afr[mi * 8 + s8];
                    #pragma unroll
                    for (int nt = 0; nt < 8; nt++) {
                        unsigned int b0 = bb[nt >> 1][(nt & 1) * 2];
                        unsigned int b1 = bb[nt >> 1][(nt & 1) * 2 + 1];
                        asm volatile(
                            "mma.sync.aligned.m16n8k16.row.col.f32.bf16.bf16.f32 "
                            "{%0,%1,%2,%3}, {%4,%5,%6,%7}, {%8,%9}, {%0,%1,%2,%3};"
                            : "+f"(acc[mi][nt][0]), "+f"(acc[mi][nt][1]),
                              "+f"(acc[mi][nt][2]), "+f"(acc[mi][nt][3])
                            : "r"(a[0]), "r"(a[1]), "r"(a[2]), "r"(a[3]),
                              "r"(b0), "r"(b1));
                    }
                }
            }

            // register rowmax (all quad lanes hold them after shfl 1,2)
            float mx[4];
            #pragma unroll
            for (int mi = 0; mi < 2; mi++) {
                float mlo = NEG_INF, mhi = NEG_INF;
                #pragma unroll
                for (int nt = 0; nt < 8; nt++) {
                    mlo = fmaxf(mlo, fmaxf(acc[mi][nt][0], acc[mi][nt][1]));
                    mhi = fmaxf(mhi, fmaxf(acc[mi][nt][2], acc[mi][nt][3]));
                }
                mlo = fmaxf(mlo, __shfl_xor_sync(0xffffffffu, mlo, 1));
                mlo = fmaxf(mlo, __shfl_xor_sync(0xffffffffu, mlo, 2));
                mhi = fmaxf(mhi, __shfl_xor_sync(0xffffffffu, mhi, 1));
                mhi = fmaxf(mhi, __shfl_xor_sync(0xffffffffu, mhi, 2));
                mx[mi * 2] = mlo;
                mx[mi * 2 + 1] = mhi;
            }
            if ((lane & 3) == 0) {
                int r0 = q0 + qr;
                rowmax[r0]      = mx[0];
                rowmax[r0 + 8]  = mx[1];
                rowmax[r0 + 16] = mx[2];
                rowmax[r0 + 24] = mx[3];
            }
            // per-row thresholds + predicated bf16 stores of flagged rows only
            {
                float t0 = topv[(q0 + qr) * 17 + 15];
                float t1 = topv[(q0 + qr + 8) * 17 + 15];
                float t2 = topv[(q0 + qr + 16) * 17 + 15];
                float t3 = topv[(q0 + qr + 24) * 17 + 15];
                int cbase = (lane & 3) * 2;
                if (mx[0] > t0) {
                    #pragma unroll
                    for (int nt = 0; nt < 8; nt++) {
                        __nv_bfloat162 h = __floats2bfloat162_rn(acc[0][nt][0], acc[0][nt][1]);
                        *(unsigned int*)&Sim[(q0 + qr) * 72 + nt * 8 + cbase] =
                            *(unsigned int*)&h;
                    }
                }
                if (mx[1] > t1) {
                    #pragma unroll
                    for (int nt = 0; nt < 8; nt++) {
                        __nv_bfloat162 h = __floats2bfloat162_rn(acc[0][nt][2], acc[0][nt][3]);
                        *(unsigned int*)&Sim[(q0 + qr + 8) * 72 + nt * 8 + cbase] =
                            *(unsigned int*)&h;
                    }
                }
                if (mx[2] > t2) {
                    #pragma unroll
                    for (int nt = 0; nt < 8; nt++) {
                        __nv_bfloat162 h = __floats2bfloat162_rn(acc[1][nt][0], acc[1][nt][1]);
                        *(unsigned int*)&Sim[(q0 + qr + 16) * 72 + nt * 8 + cbase] =
                            *(unsigned int*)&h;
                    }
                }
                if (mx[3] > t3) {
                    #pragma unroll
                    for (int nt = 0; nt < 8; nt++) {
                        __nv_bfloat162 h = __floats2bfloat162_rn(acc[1][nt][2], acc[1][nt][3]);
                        *(unsigned int*)&Sim[(q0 + qr + 24) * 72 + nt * 8 + cbase] =
                            *(unsigned int*)&h;
                    }
                }
            }
            __syncwarp();
            // scan flagged row (thread owns query tid)
            {
                float thr = topv[tid * 17 + TOPK - 1];
                if (rowmax[tid] > thr) {
                    const unsigned int* rowu = (const unsigned int*)(Sim + tid * 72);
                    for (int j2 = 0; j2 < 32; j2++) {
                        unsigned int u = rowu[j2];
                        __nv_bfloat162 h = *(__nv_bfloat162*)&u;
                        #pragma unroll
                        for (int e = 0; e < 2; e++) {
                            float vv = __bfloat162float(e ? h.y : h.x);
                            if (vv > thr) {
                                int kidx = n0g + j2 * 2 + e;
                                int pos = TOPK - 1;
                                while (pos > 0 && topv[tid * 17 + pos - 1] < vv) {
                                    topv[tid * 17 + pos] = topv[tid * 17 + pos - 1];
                                    topi[tid * 17 + pos] = topi[tid * 17 + pos - 1];
                                    pos--;
                                }
                                topv[tid * 17 + pos] = vv;
                                topi[tid * 17 + pos] = kidx;
                                thr = topv[tid * 17 + TOPK - 1];
                            }
                        }
                    }
                }
            }
            __syncwarp();
        }
        __syncthreads();

        {
            int b = qbase + tid;
            unsigned long long* dst = &g_cand[((size_t)b * NCHUNKS + chunk) * TOPK];
            #pragma unroll
            for (int j = 0; j < TOPK; j++) {
                unsigned long long hv =
                    (unsigned long long)fkey(topv[tid * 17 + j]) << 32;
                dst[j] = hv | (unsigned long long)(0xFFFFFFFFu -
                                (unsigned int)topi[tid * 17 + j]);
            }
        }
    }
}

// -------- kernel 4: merge approx top-64, exact rescore, output --------
#define NCAND (NCHUNKS * TOPK)   // 1568

__global__ void __launch_bounds__(128)
k_rescore(const float* __restrict__ keys, const float* __restrict__ values,
          float* __restrict__ out) {
    __shared__ unsigned long long cb[NCAND];
    __shared__ unsigned long long wred[4];
    __shared__ unsigned long long mtop[MTOP];
    __shared__ unsigned long long exact[MTOP];
    __shared__ float qsh[DDIM];
    __shared__ float smv[TOPK];
    __shared__ int   sidx[TOPK];
    __shared__ float w[TOPK];

    int b = blockIdx.x, tid = threadIdx.x;
    int lane = tid & 31, warp = tid >> 5;

    const unsigned long long* src = &g_cand[(size_t)b * NCAND];
    for (int i = tid; i < NCAND; i += 128) cb[i] = src[i];
    qsh[tid] = g_qn[b * DDIM + tid];
    __syncthreads();

    for (int r = 0; r < MTOP; r++) {
        unsigned long long m = 0ull;
        for (int i = tid; i < NCAND; i += 128) {
            unsigned long long v = cb[i];
            if (v > m) m = v;
        }
        #pragma unroll
        for (int o = 16; o; o >>= 1) {
            unsigned long long t = __shfl_xor_sync(0xffffffffu, m, o);
            if (t > m) m = t;
        }
        if (lane == 0) wred[warp] = m;
        __syncthreads();
        unsigned long long top = wred[0];
        #pragma unroll
        for (int i = 1; i < 4; i++) if (wred[i] > top) top = wred[i];
        for (int i = tid; i < NCAND; i += 128)
            if (cb[i] == top) cb[i] = 0ull;
        if (tid == 0) mtop[r] = top;
        __syncthreads();
    }

    for (int r = warp; r < MTOP; r += 4) {
        unsigned long long pk = mtop[r];
        int key = (int)(0xFFFFFFFFu - (unsigned int)(pk & 0xFFFFFFFFu));
        float4 kv = ((const float4*)(keys + (size_t)key * DDIM))[lane];
        float4 qv = *(const float4*)&qsh[lane * 4];
        float d = kv.x * qv.x + kv.y * qv.y + kv.z * qv.z + kv.w * qv.w;
        #pragma unroll
        for (int o = 16; o; o >>= 1) d += __shfl_xor_sync(0xffffffffu, d, o);
        if (lane == 0) {
            float ex = d * g_scale[key];
            exact[r] = ((unsigned long long)fkey(ex) << 32) |
                       (unsigned long long)(0xFFFFFFFFu - (unsigned int)key);
        }
    }
    __syncthreads();

    if (warp == 0) {
        unsigned long long va = exact[lane];
        unsigned long long vb = exact[lane + 32];
        for (int r = 0; r < TOPK; r++) {
            unsigned long long m = (va > vb) ? va : vb;
            #pragma unroll
            for (int o = 16; o; o >>= 1) {
                unsigned long long t = __shfl_xor_sync(0xffffffffu, m, o);
                if (t > m) m = t;
            }
            if (va == m) va = 0ull;
            else if (vb == m) vb = 0ull;
            if (lane == 0) {
                float s = funkey((unsigned int)(m >> 32));
                int idx = (int)(0xFFFFFFFFu - (unsigned int)(m & 0xFFFFFFFFu));
                smv[r] = (s >= 0.0f) ? s : 0.0f;
                sidx[r] = idx;
            }
        }
        if (lane == 0) {
            float su = 0.0f;
            #pragma unroll
            for (int r = 0; r < TOPK; r++) su += smv[r];
            su += 1e-8f;
            #pragma unroll
            for (int r = 0; r < TOPK; r++) w[r] = smv[r] / su;
        }
    }
    __syncthreads();

    for (int j = tid; j < HFDIM; j += 128) {
        float a = 0.0f;
        #pragma unroll
        for (int r = 0; r < TOPK; r++)
            a += w[r] * values[(size_t)sidx[r] * HFDIM + j];
        out[(size_t)b * HFDIM + j] = a;
    }
}

// -------- launch --------
extern "C" void kernel_launch(void* const* d_in, const int* in_sizes, int n_in,
                              void* d_out, int out_size) {
    const float* query  = (const float*)d_in[0];
    const float* keys   = (const float*)d_in[1];
    const float* values = (const float*)d_in[2];
    const void*  ts     = d_in[3];
    const int*   gsp    = (n_in > 4) ? (const int*)d_in[4] : nullptr;

    cudaFuncSetAttribute(k_filter,
                         cudaFuncAttributeMaxDynamicSharedMemorySize, SMEM_SZ);

    k_detect<<<1, 32>>>((const unsigned int*)ts);
    k_normq<<<BQ, DDIM>>>(query);
    k_scale<<<(NKEYS * 32 + 255) / 256, 256>>>(keys, ts, gsp, gsp != nullptr);
    k_filter<<<GRID_F, FTHR, SMEM_SZ>>>();
    k_rescore<<<BQ, 128>>>(keys, values, (float*)d_out);
}

// round 11
// speedup vs baseline: 3.5304x; 1.0066x over previous
#include <cuda_runtime.h>
#include <cuda_fp16.h>
#include <math.h>

// Problem constants
#define BQ      1024
#define DDIM    128
#define NKEYS   200000
#define HFDIM   168
#define TOPK    16
#define MTOP    64
#define CHUNK   2048
#define NCHUNKS 98           // 97*2048 + 1344; every 64-key tile full
#define QTILES  8
#define NPAIRS  (QTILES*NCHUNKS)   // 784
#define FTHR    128
#define GRID_F  444          // 3 blocks/SM persistent

// -------- filter kernel SMEM layout (bytes) --------
// [Ks fp16 2x64x136 (34816, unioned with Qs 128x136) | Sim fp16 128x72 |
//  topv f32 128x17 | topi 128x17 | rowmax 128 | work]
#define KBUF_B    17408
#define OFF_SIM   34816
#define OFF_TOPV  53248
#define OFF_TOPI  61952
#define OFF_RMAX  70656
#define OFF_WORK  71168
#define SMEM_SZ   71184

// -------- scratch --------
__device__ float g_qn[BQ * DDIM];
__device__ __half g_qh[BQ * DDIM];
__device__ __half g_khd[(size_t)NKEYS * DDIM];
__device__ float g_scale[NKEYS];
__device__ unsigned long long g_cand[(size_t)BQ * NCHUNKS * TOPK];
__device__ int g_ts64;
__device__ unsigned int g_work;

// -------- helpers --------
__device__ __forceinline__ unsigned int fkey(float f) {
    unsigned int u = __float_as_uint(f);
    return (u & 0x80000000u) ? ~u : (u | 0x80000000u);
}
__device__ __forceinline__ float funkey(unsigned int u) {
    return (u & 0x80000000u) ? __uint_as_float(u ^ 0x80000000u)
                             : __uint_as_float(~u);
}
__device__ __forceinline__ unsigned int su32(const void* p) {
    unsigned int r;
    asm("{.reg .u64 t; cvta.to.shared.u64 t, %1; cvt.u32.u64 %0, t;}"
        : "=r"(r) : "l"(p));
    return r;
}
__device__ __forceinline__ void cp16(unsigned int dst, const void* src) {
    asm volatile("cp.async.cg.shared.global [%0], [%1], 16;"
                 :: "r"(dst), "l"(src));
}
#define CP_COMMIT() asm volatile("cp.async.commit_group;")
#define CP_WAIT0()  asm volatile("cp.async.wait_group 0;" ::: "memory")
#define NEG_INF __int_as_float(0xff800000)

#define LDSM_X4(f, ad) \
    asm volatile("ldmatrix.sync.aligned.m8n8.x4.shared.b16 {%0,%1,%2,%3}, [%4];" \
        : "=r"((f)[0]), "=r"((f)[1]), "=r"((f)[2]), "=r"((f)[3]) : "r"(ad))
#define MMA_F16(c0, c1, a, b0, b1) \
    asm volatile("mma.sync.aligned.m16n8k16.row.col.f16.f16.f16.f16 " \
        "{%0,%1}, {%2,%3,%4,%5}, {%6,%7}, {%0,%1};" \
        : "+r"(c0), "+r"(c1) \
        : "r"((a)[0]), "r"((a)[1]), "r"((a)[2]), "r"((a)[3]), "r"(b0), "r"(b1))

// -------- kernel 0: detect ts dtype + reset work counter --------
__global__ void k_detect(const unsigned int* tsw) {
    if (threadIdx.x == 0) {
        int all0 = 1;
        for (int i = 0; i < 64; i++)
            if (tsw[2 * i + 1] != 0u) { all0 = 0; break; }
        g_ts64 = all0;
        g_work = 0u;
    }
}

// -------- kernel 1: normalize queries (fp32 + fp16) --------
__global__ void k_normq(const float* __restrict__ query) {
    int b = blockIdx.x;
    int d = threadIdx.x;
    float v = query[b * DDIM + d];
    float s = v * v;
    #pragma unroll
    for (int o = 16; o; o >>= 1) s += __shfl_xor_sync(0xffffffffu, s, o);
    __shared__ float ws[4];
    if ((d & 31) == 0) ws[d >> 5] = s;
    __syncthreads();
    float tot = ws[0] + ws[1] + ws[2] + ws[3];
    float n = fmaxf(sqrtf(tot), 1e-12f);
    float q = v / n;
    g_qn[b * DDIM + d] = q;
    g_qh[b * DDIM + d] = __float2half_rn(q);
}

// -------- kernel 2: per-key scale + fp16 decayed keys --------
__global__ void k_scale(const float* __restrict__ keys, const void* ts,
                        const int* gsp, int has_gs) {
    int gw = (blockIdx.x * blockDim.x + threadIdx.x) >> 5;
    int lane = threadIdx.x & 31;
    if (gw >= NKEYS) return;
    float4 a = ((const float4*)(keys + (size_t)gw * DDIM))[lane];
    float s = a.x * a.x + a.y * a.y + a.z * a.z + a.w * a.w;
    #pragma unroll
    for (int o = 16; o; o >>= 1) s += __shfl_xor_sync(0xffffffffu, s, o);
    float sc;
    if (lane == 0) {
        long long t = g_ts64 ? ((const long long*)ts)[gw]
                             : (long long)((const int*)ts)[gw];
        int gs = has_gs ? gsp[0] : 1000;
        float age = (float)(gs - (int)t);
        float dec = powf(0.995f, age);
        float nr = fmaxf(sqrtf(s), 1e-12f);
        sc = dec / nr;
        g_scale[gw] = sc;
    }
    sc = __shfl_sync(0xffffffffu, sc, 0);
    __half2 p0 = __floats2half2_rn(a.x * sc, a.y * sc);
    __half2 p1 = __floats2half2_rn(a.z * sc, a.w * sc);
    uint2 pk = make_uint2(*(unsigned int*)&p0, *(unsigned int*)&p1);
    *(uint2*)&g_khd[(size_t)gw * DDIM + lane * 4] = pk;
}

// -------- kernel 3: fp16 MMA filter, cp.async + LDSM pipelines --------
__global__ void __launch_bounds__(FTHR, 3)
k_filter() {
    extern __shared__ __align__(16) unsigned char sm[];
    __half* Ks  = (__half*)sm;                     // [2][64][136]
    __half* Qs  = (__half*)sm;                     // [128][136] (prologue union)
    __half* Sim = (__half*)(sm + OFF_SIM);         // [128][72]
    float* topv   = (float*)(sm + OFF_TOPV);       // [128][17]
    int*   topi   = (int*)(sm + OFF_TOPI);         // [128][17]
    float* rowmax = (float*)(sm + OFF_RMAX);       // [128]
    unsigned int* swork = (unsigned int*)(sm + OFF_WORK);

    unsigned int ks_base = su32(Ks);
    int tid  = threadIdx.x;
    int warp = tid >> 5;
    int lane = tid & 31;
    int q0 = warp * 32;
    int qr = lane >> 2;

    for (;;) {
        __syncthreads();
        if (tid == 0) *swork = atomicAdd(&g_work, 1u);
        __syncthreads();
        unsigned int p = *swork;
        if (p >= NPAIRS) break;
        int chunk = p >> 3;
        int qtile = p & 7;
        int qbase = qtile * 128;
        int c0 = chunk * CHUNK;
        int ntiles = (chunk == NCHUNKS - 1) ? 21 : 32;

        #pragma unroll
        for (int j = 0; j < TOPK; j++) {
            topv[tid * 17 + j] = NEG_INF;
            topi[tid * 17 + j] = 0;
        }
        // prologue: stage Q [128][128] fp16 through the K double-buffer region
        for (int i = tid; i < 128 * 16; i += FTHR) {
            int row = i >> 4, c = i & 15;
            *(uint4*)(Qs + row * 136 + c * 8) =
                *(const uint4*)(g_qh + (qbase + row) * DDIM + c * 8);
        }
        __syncthreads();
        unsigned int afr[16][4];
        #pragma unroll
        for (int s8 = 0; s8 < 8; s8++) {
            #pragma unroll
            for (int mi = 0; mi < 2; mi++) {
                int row = q0 + mi * 16 + (lane & 15);
                int col = s8 * 16 + ((lane >> 4) << 3);
                LDSM_X4(afr[mi * 8 + s8], su32(Qs + row * 136 + col));
            }
        }
        __syncthreads();   // A frags read before K tile 0 overwrites

        // issue K tile 0 into buffer 0
        #pragma unroll
        for (int it = 0; it < 8; it++) {
            int i = tid + it * FTHR;
            int row = i >> 4, c = i & 15;
            cp16(ks_base + row * 272 + c * 16,
                 g_khd + (size_t)(c0 + row) * DDIM + c * 8);
        }
        CP_COMMIT();

        for (int t = 0; t < ntiles; t++) {
            int n0g = c0 + t * 64;
            unsigned int kb = ks_base + (t & 1) * KBUF_B;
            CP_WAIT0();
            __syncthreads();   // tile t ready; all warps done with tile t-1

            if (t + 1 < ntiles) {
                int n1 = c0 + (t + 1) * 64;
                unsigned int ob = ks_base + ((t + 1) & 1) * KBUF_B;
                #pragma unroll
                for (int it = 0; it < 8; it++) {
                    int i = tid + it * FTHR;
                    int row = i >> 4, c = i & 15;
                    cp16(ob + row * 272 + c * 16,
                         g_khd + (size_t)(n1 + row) * DDIM + c * 8);
                }
            }
            CP_COMMIT();

            // fp16-acc MMA over 8 k-steps; B frags double-buffered
            unsigned int acc[2][8][2];
            #pragma unroll
            for (int mi = 0; mi < 2; mi++)
                #pragma unroll
                for (int nt = 0; nt < 8; nt++) {
                    acc[mi][nt][0] = 0u;
                    acc[mi][nt][1] = 0u;
                }
            unsigned int bb[2][4][4];
            {
                int prow = (lane & 7) + ((lane >> 4) << 3);
                int pcol = ((lane >> 3) & 1) << 3;
                #pragma unroll
                for (int g = 0; g < 4; g++)
                    LDSM_X4(bb[0][g], kb + (g * 16 + prow) * 272 + pcol * 2);
            }
            #pragma unroll
            for (int s8 = 0; s8 < 8; s8++) {
                int cur = s8 & 1;
                if (s8 < 7) {
                    int ds = (s8 + 1) * 16;
                    int prow = (lane & 7) + ((lane >> 4) << 3);
                    int pcol = ds + (((lane >> 3) & 1) << 3);
                    #pragma unroll
                    for (int g = 0; g < 4; g++)
                        LDSM_X4(bb[cur ^ 1][g], kb + (g * 16 + prow) * 272 + pcol * 2);
                }
                #pragma unroll
                for (int mi = 0; mi < 2; mi++) {
                    const unsigned int* a = afr[mi * 8 + s8];
                    #pragma unroll
                    for (int nt = 0; nt < 8; nt++) {
                        unsigned int b0 = bb[cur][nt >> 1][(nt & 1) * 2];
                        unsigned int b1 = bb[cur][nt >> 1][(nt & 1) * 2 + 1];
                        MMA_F16(acc[mi][nt][0], acc[mi][nt][1], a, b0, b1);
                    }
                }
            }

            // register rowmax via half2 max trees + quad shfl
            float mx[4];
            #pragma unroll
            for (int mi = 0; mi < 2; mi++) {
                #pragma unroll
                for (int e = 0; e < 2; e++) {
                    __half2 m = *(__half2*)&acc[mi][0][e];
                    #pragma unroll
                    for (int nt = 1; nt < 8; nt++)
                        m = __hmax2(m, *(__half2*)&acc[mi][nt][e]);
                    float mv = fmaxf(__low2float(m), __high2float(m));
                    mv = fmaxf(mv, __shfl_xor_sync(0xffffffffu, mv, 1));
                    mv = fmaxf(mv, __shfl_xor_sync(0xffffffffu, mv, 2));
                    mx[mi * 2 + e] = mv;
                }
            }
            if ((lane & 3) == 0) {
                int r0 = q0 + qr;
                rowmax[r0]      = mx[0];
                rowmax[r0 + 8]  = mx[1];
                rowmax[r0 + 16] = mx[2];
                rowmax[r0 + 24] = mx[3];
            }
            // predicated raw-u32 Sim stores of flagged rows only
            {
                float t0 = topv[(q0 + qr) * 17 + 15];
                float t1 = topv[(q0 + qr + 8) * 17 + 15];
                float t2 = topv[(q0 + qr + 16) * 17 + 15];
                float t3 = topv[(q0 + qr + 24) * 17 + 15];
                int cbase = (lane & 3) * 2;
                if (mx[0] > t0) {
                    #pragma unroll
                    for (int nt = 0; nt < 8; nt++)
                        *(unsigned int*)&Sim[(q0 + qr) * 72 + nt * 8 + cbase] =
                            acc[0][nt][0];
                }
                if (mx[1] > t1) {
                    #pragma unroll
                    for (int nt = 0; nt < 8; nt++)
                        *(unsigned int*)&Sim[(q0 + qr + 8) * 72 + nt * 8 + cbase] =
                            acc[0][nt][1];
                }
                if (mx[2] > t2) {
                    #pragma unroll
                    for (int nt = 0; nt < 8; nt++)
                        *(unsigned int*)&Sim[(q0 + qr + 16) * 72 + nt * 8 + cbase] =
                            acc[1][nt][0];
                }
                if (mx[3] > t3) {
                    #pragma unroll
                    for (int nt = 0; nt < 8; nt++)
                        *(unsigned int*)&Sim[(q0 + qr + 24) * 72 + nt * 8 + cbase] =
                            acc[1][nt][1];
                }
            }
            __syncwarp();
            // scan flagged row (thread owns query tid)
            {
                float thr = topv[tid * 17 + TOPK - 1];
                if (rowmax[tid] > thr) {
                    const unsigned int* rowu = (const unsigned int*)(Sim + tid * 72);
                    for (int j2 = 0; j2 < 32; j2++) {
                        unsigned int u = rowu[j2];
                        __half2 h = *(__half2*)&u;
                        #pragma unroll
                        for (int e = 0; e < 2; e++) {
                            float vv = e ? __high2float(h) : __low2float(h);
                            if (vv > thr) {
                                int kidx = n0g + j2 * 2 + e;
                                int pos = TOPK - 1;
                                while (pos > 0 && topv[tid * 17 + pos - 1] < vv) {
                                    topv[tid * 17 + pos] = topv[tid * 17 + pos - 1];
                                    topi[tid * 17 + pos] = topi[tid * 17 + pos - 1];
                                    pos--;
                                }
                                topv[tid * 17 + pos] = vv;
                                topi[tid * 17 + pos] = kidx;
                                thr = topv[tid * 17 + TOPK - 1];
                            }
                        }
                    }
                }
            }
            __syncwarp();
        }
        __syncthreads();

        {
            int b = qbase + tid;
            unsigned long long* dst = &g_cand[((size_t)b * NCHUNKS + chunk) * TOPK];
            #pragma unroll
            for (int j = 0; j < TOPK; j++) {
                unsigned long long hv =
                    (unsigned long long)fkey(topv[tid * 17 + j]) << 32;
                dst[j] = hv | (unsigned long long)(0xFFFFFFFFu -
                                (unsigned int)topi[tid * 17 + j]);
            }
        }
    }
}

// -------- kernel 4: merge approx top-64, exact rescore, output --------
#define NCAND (NCHUNKS * TOPK)   // 1568

__global__ void __launch_bounds__(128)
k_rescore(const float* __restrict__ keys, const float* __restrict__ values,
          float* __restrict__ out) {
    __shared__ unsigned long long cb[NCAND];
    __shared__ unsigned long long wred[4];
    __shared__ unsigned long long mtop[MTOP];
    __shared__ unsigned long long exact[MTOP];
    __shared__ float qsh[DDIM];
    __shared__ float smv[TOPK];
    __shared__ int   sidx[TOPK];
    __shared__ float w[TOPK];

    int b = blockIdx.x, tid = threadIdx.x;
    int lane = tid & 31, warp = tid >> 5;

    const unsigned long long* src = &g_cand[(size_t)b * NCAND];
    for (int i = tid; i < NCAND; i += 128) cb[i] = src[i];
    qsh[tid] = g_qn[b * DDIM + tid];
    __syncthreads();

    for (int r = 0; r < MTOP; r++) {
        unsigned long long m = 0ull;
        for (int i = tid; i < NCAND; i += 128) {
            unsigned long long v = cb[i];
            if (v > m) m = v;
        }
        #pragma unroll
        for (int o = 16; o; o >>= 1) {
            unsigned long long t = __shfl_xor_sync(0xffffffffu, m, o);
            if (t > m) m = t;
        }
        if (lane == 0) wred[warp] = m;
        __syncthreads();
        unsigned long long top = wred[0];
        #pragma unroll
        for (int i = 1; i < 4; i++) if (wred[i] > top) top = wred[i];
        for (int i = tid; i < NCAND; i += 128)
            if (cb[i] == top) cb[i] = 0ull;
        if (tid == 0) mtop[r] = top;
        __syncthreads();
    }

    for (int r = warp; r < MTOP; r += 4) {
        unsigned long long pk = mtop[r];
        int key = (int)(0xFFFFFFFFu - (unsigned int)(pk & 0xFFFFFFFFu));
        float4 kv = ((const float4*)(keys + (size_t)key * DDIM))[lane];
        float4 qv = *(const float4*)&qsh[lane * 4];
        float d = kv.x * qv.x + kv.y * qv.y + kv.z * qv.z + kv.w * qv.w;
        #pragma unroll
        for (int o = 16; o; o >>= 1) d += __shfl_xor_sync(0xffffffffu, d, o);
        if (lane == 0) {
            float ex = d * g_scale[key];
            exact[r] = ((unsigned long long)fkey(ex) << 32) |
                       (unsigned long long)(0xFFFFFFFFu - (unsigned int)key);
        }
    }
    __syncthreads();

    if (warp == 0) {
        unsigned long long va = exact[lane];
        unsigned long long vb = exact[lane + 32];
        for (int r = 0; r < TOPK; r++) {
            unsigned long long m = (va > vb) ? va : vb;
            #pragma unroll
            for (int o = 16; o; o >>= 1) {
                unsigned long long t = __shfl_xor_sync(0xffffffffu, m, o);
                if (t > m) m = t;
            }
            if (va == m) va = 0ull;
            else if (vb == m) vb = 0ull;
            if (lane == 0) {
                float s = funkey((unsigned int)(m >> 32));
                int idx = (int)(0xFFFFFFFFu - (unsigned int)(m & 0xFFFFFFFFu));
                smv[r] = (s >= 0.0f) ? s : 0.0f;
                sidx[r] = idx;
            }
        }
        if (lane == 0) {
            float su = 0.0f;
            #pragma unroll
            for (int r = 0; r < TOPK; r++) su += smv[r];
            su += 1e-8f;
            #pragma unroll
            for (int r = 0; r < TOPK; r++) w[r] = smv[r] / su;
        }
    }
    __syncthreads();

    for (int j = tid; j < HFDIM; j += 128) {
        float a = 0.0f;
        #pragma unroll
        for (int r = 0; r < TOPK; r++)
            a += w[r] * values[(size_t)sidx[r] * HFDIM + j];
        out[(size_t)b * HFDIM + j] = a;
    }
}

// -------- launch --------
extern "C" void kernel_launch(void* const* d_in, const int* in_sizes, int n_in,
                              void* d_out, int out_size) {
    const float* query  = (const float*)d_in[0];
    const float* keys   = (const float*)d_in[1];
    const float* values = (const float*)d_in[2];
    const void*  ts     = d_in[3];
    const int*   gsp    = (n_in > 4) ? (const int*)d_in[4] : nullptr;

    cudaFuncSetAttribute(k_filter,
                         cudaFuncAttributeMaxDynamicSharedMemorySize, SMEM_SZ);

    k_detect<<<1, 32>>>((const unsigned int*)ts);
    k_normq<<<BQ, DDIM>>>(query);
    k_scale<<<(NKEYS * 32 + 255) / 256, 256>>>(keys, ts, gsp, gsp != nullptr);
    k_filter<<<GRID_F, FTHR, SMEM_SZ>>>();
    k_rescore<<<BQ, 128>>>(keys, values, (float*)d_out);
}